// round 14
// baseline (speedup 1.0000x reference)
#include <cuda_runtime.h>
#include <math.h>
#include <stdint.h>

#define N_NODES 20000
#define N_EDGES 320000
#define N_ITEMS (N_EDGES + N_NODES)

// ---------------- scratch (device globals; no allocs allowed) ----------------
__device__ float g_xl[N_NODES * 256];   // layer xl; later reused as A|B for classifier
__device__ float g_xr[N_NODES * 256];
__device__ float g_zv1[N_NODES * 128];
__device__ float g_zv2[N_NODES * 128];
__device__ float g_gi[N_NODES * 384];
__device__ float g_h[N_NODES * 128];
__device__ float g_Wt[128 * 384];
__device__ float g_easum[16];
__device__ uint32_t g_wc2p[8192];       // packed tf32 Wc2 for classifier
__device__ int g_deg[N_NODES];
__device__ int g_fill[N_NODES];
__device__ int g_rowptr[N_NODES + 1];
__device__ int g_csr_src[N_ITEMS];
__device__ int g_csr_eid[N_ITEMS];

// ---------------- utility kernels ----------------
__global__ void zero_f(float* p, int n) {
    int i = blockIdx.x * blockDim.x + threadIdx.x;
    if (i < n) p[i] = 0.f;
}
__global__ void zero2_i(int* p0, int* p1, int n) {
    int i = blockIdx.x * blockDim.x + threadIdx.x;
    if (i < n) { p0[i] = 0; p1[i] = 0; }
}

// column sums of edge_attr [E,16] -> easum[16], float4 vectorized
__global__ void ea_colsum4(const float* __restrict__ ea, float* easum) {
    __shared__ float sh[16];
    if (threadIdx.x < 16) sh[threadIdx.x] = 0.f;
    __syncthreads();
    int g = blockIdx.x * blockDim.x + threadIdx.x;
    int stride = gridDim.x * blockDim.x;
    int q = g & 3;
    int slot = g >> 2;
    int ns = stride >> 2;
    float4 acc = make_float4(0.f, 0.f, 0.f, 0.f);
    for (int e = slot; e < N_EDGES; e += ns) {
        float4 v = *(const float4*)&ea[(size_t)e * 16 + q * 4];
        acc.x += v.x; acc.y += v.y; acc.z += v.z; acc.w += v.w;
    }
    atomicAdd(&sh[q * 4 + 0], acc.x);
    atomicAdd(&sh[q * 4 + 1], acc.y);
    atomicAdd(&sh[q * 4 + 2], acc.z);
    atomicAdd(&sh[q * 4 + 3], acc.w);
    __syncthreads();
    if (threadIdx.x < 16) atomicAdd(&easum[threadIdx.x], sh[threadIdx.x]);
}

// transpose W_ih [384,128] -> Wt [128,384]
__global__ void transpose_wih(const float* __restrict__ W, float* __restrict__ Wt) {
    int i = blockIdx.x * blockDim.x + threadIdx.x;
    if (i < 384 * 128) {
        int j = i / 128, k = i % 128;
        Wt[k * 384 + j] = W[i];
    }
}

// ---------------- tf32 helpers ----------------
__device__ __forceinline__ uint32_t f2tf32(float x) {
    uint32_t r;
    asm("cvt.rna.tf32.f32 %0, %1;" : "=r"(r) : "f"(x));
    return r;
}
__device__ __forceinline__ void mma_tf32(float* c, const uint32_t* a, const uint32_t* b) {
    asm volatile(
        "mma.sync.aligned.m16n8k8.row.col.f32.tf32.tf32.f32 "
        "{%0,%1,%2,%3}, {%4,%5,%6,%7}, {%8,%9}, {%0,%1,%2,%3};"
        : "+f"(c[0]), "+f"(c[1]), "+f"(c[2]), "+f"(c[3])
        : "r"(a[0]), "r"(a[1]), "r"(a[2]), "r"(a[3]), "r"(b[0]), "r"(b[1]));
}

// pack Wc2 [128k][64n] into tf32 words laid out [g=k/8][n][s], s=((k&3)<<1)|((k>>2)&1)
__global__ void pack_wc2(const float* __restrict__ Wc2, uint32_t* __restrict__ wc2p) {
    int w = blockIdx.x * blockDim.x + threadIdx.x;
    if (w < 8192) {
        int g = w >> 9, rem = w & 511, n = rem >> 3, s = rem & 7;
        int k = g * 8 + (s & 1) * 4 + (s >> 1);
        wc2p[w] = f2tf32(Wc2[k * 64 + n]);
    }
}

// ---------------- CSR build ----------------
__global__ void deg_count(const int* __restrict__ dst, int* __restrict__ deg) {
    int i = blockIdx.x * blockDim.x + threadIdx.x;
    if (i < N_EDGES) atomicAdd(&deg[dst[i]], 1);
}

__global__ void scan_kernel(const int* __restrict__ deg, int* __restrict__ rowptr) {
    __shared__ int ssum[1024];
    const int CH = 20;
    int t = threadIdx.x;
    int base = t * CH;
    int s = 0;
    for (int i = 0; i < CH; i++) {
        int node = base + i;
        if (node < N_NODES) s += deg[node] + 1;
    }
    ssum[t] = s;
    __syncthreads();
    for (int off = 1; off < 1024; off <<= 1) {
        int v = (t >= off) ? ssum[t - off] : 0;
        __syncthreads();
        ssum[t] += v;
        __syncthreads();
    }
    int run = (t == 0) ? 0 : ssum[t - 1];
    for (int i = 0; i < CH; i++) {
        int node = base + i;
        if (node < N_NODES) {
            rowptr[node] = run;
            run += deg[node] + 1;
        } else if (node == N_NODES) {
            rowptr[node] = run;
        }
    }
}

__global__ void scatter_kernel(const int* __restrict__ src, const int* __restrict__ dst,
                               const int* __restrict__ rowptr, int* __restrict__ fill,
                               int* __restrict__ csr_src, int* __restrict__ csr_eid) {
    int i = blockIdx.x * blockDim.x + threadIdx.x;
    if (i >= N_ITEMS) return;
    int s, d;
    if (i < N_EDGES) { s = src[i]; d = dst[i]; }
    else { s = i - N_EDGES; d = s; }
    int pos = rowptr[d] + atomicAdd(&fill[d], 1);
    csr_src[pos] = s;
    csr_eid[pos] = i;
}

// ---------------- tf32 tensor-core GEMM, dual-output, reg-prefetch pipelined ----------
__global__ __launch_bounds__(256) void gemm_tc2(
    const float* __restrict__ A,
    const float* __restrict__ B0, const float* __restrict__ bias0, float* __restrict__ C0,
    const float* __restrict__ B1, const float* __restrict__ bias1, float* __restrict__ C1,
    int n, int K, int M, int gx0) {
    __shared__ uint32_t As[16][132];
    __shared__ uint32_t Bs[16][132];
    const int tid = threadIdx.x;
    const int warp = tid >> 5, lane = tid & 31;
    const int warpM = (warp >> 1) * 32;
    const int warpN = (warp & 1) * 64;
    int bx = blockIdx.x;
    const float* B;
    const float* bias;
    float* C;
    if (bx < gx0) { B = B0; bias = bias0; C = C0; }
    else { bx -= gx0; B = B1; bias = bias1; C = C1; }
    const int row0 = blockIdx.y * 128, col0 = bx * 128;
    const int lk = lane & 3;
    const int lr = lane >> 2;

    int arow[2], aq[2], brow[2], bq[2];
#pragma unroll
    for (int i = 0; i < 2; i++) {
        int idx = tid * 2 + i;
        arow[i] = idx >> 2;
        aq[i] = idx & 3;
        brow[i] = idx >> 5;
        bq[i] = idx & 31;
    }

    float acc[2][8][4] = {};
    float4 pa[2], pb[2];

#pragma unroll
    for (int i = 0; i < 2; i++) {
        int r = row0 + arow[i];
        pa[i] = (r < n) ? *(const float4*)&A[(size_t)r * K + aq[i] * 4]
                        : make_float4(0.f, 0.f, 0.f, 0.f);
        pb[i] = *(const float4*)&B[(size_t)brow[i] * M + col0 + bq[i] * 4];
    }

    for (int k0 = 0; k0 < K; k0 += 16) {
#pragma unroll
        for (int i = 0; i < 2; i++) {
            As[aq[i] * 4 + 0][arow[i]] = f2tf32(pa[i].x);
            As[aq[i] * 4 + 1][arow[i]] = f2tf32(pa[i].y);
            As[aq[i] * 4 + 2][arow[i]] = f2tf32(pa[i].z);
            As[aq[i] * 4 + 3][arow[i]] = f2tf32(pa[i].w);
            uint4 tv;
            tv.x = f2tf32(pb[i].x); tv.y = f2tf32(pb[i].y);
            tv.z = f2tf32(pb[i].z); tv.w = f2tf32(pb[i].w);
            *(uint4*)&Bs[brow[i]][bq[i] * 4] = tv;
        }
        __syncthreads();
        if (k0 + 16 < K) {
#pragma unroll
            for (int i = 0; i < 2; i++) {
                int r = row0 + arow[i];
                pa[i] = (r < n) ? *(const float4*)&A[(size_t)r * K + k0 + 16 + aq[i] * 4]
                                : make_float4(0.f, 0.f, 0.f, 0.f);
                pb[i] = *(const float4*)&B[(size_t)(k0 + 16 + brow[i]) * M + col0 + bq[i] * 4];
            }
        }
#pragma unroll
        for (int ks = 0; ks < 16; ks += 8) {
            uint32_t af[2][4];
#pragma unroll
            for (int mt = 0; mt < 2; mt++) {
                int m = warpM + mt * 16 + lr;
                af[mt][0] = As[ks + lk][m];
                af[mt][1] = As[ks + lk][m + 8];
                af[mt][2] = As[ks + lk + 4][m];
                af[mt][3] = As[ks + lk + 4][m + 8];
            }
            uint32_t bf[8][2];
#pragma unroll
            for (int nt = 0; nt < 8; nt++) {
                int nn = warpN + nt * 8 + lr;
                bf[nt][0] = Bs[ks + lk][nn];
                bf[nt][1] = Bs[ks + lk + 4][nn];
            }
#pragma unroll
            for (int mt = 0; mt < 2; mt++)
#pragma unroll
                for (int nt = 0; nt < 8; nt++) mma_tf32(acc[mt][nt], af[mt], bf[nt]);
        }
        __syncthreads();
    }
#pragma unroll
    for (int mt = 0; mt < 2; mt++) {
        int r0 = row0 + warpM + mt * 16 + lr;
        int r1 = r0 + 8;
#pragma unroll
        for (int nt = 0; nt < 8; nt++) {
            int c = col0 + warpN + nt * 8 + lk * 2;
            float b0 = bias ? bias[c] : 0.f;
            float b1 = bias ? bias[c + 1] : 0.f;
            if (r0 < n) {
                float2 v = make_float2(acc[mt][nt][0] + b0, acc[mt][nt][1] + b1);
                *(float2*)&C[(size_t)r0 * M + c] = v;
            }
            if (r1 < n) {
                float2 v = make_float2(acc[mt][nt][2] + b0, acc[mt][nt][3] + b1);
                *(float2*)&C[(size_t)r1 * M + c] = v;
            }
        }
    }
}

// ---------------- GAT layer 1, head-split: warp = (node, head), EP=4 ----------------
// Two warps per node (one per head). Each warp handles 128 cols (1 float4/lane),
// EP=4 edges share each We load. Head-1 warp deposits normalized agg in smem;
// head-0 warp combines (mean+bias), LayerNorm, ELU, stores.
#define L1_EP 4
__global__ __launch_bounds__(256) void gat_l1_hsplit(
    const int* __restrict__ rowptr, const int* __restrict__ csr_src,
    const int* __restrict__ csr_eid, const float* __restrict__ ea,
    const float* __restrict__ We, const float* __restrict__ easum, float invE,
    const float* __restrict__ xl, const float* __restrict__ xr,
    const float* __restrict__ att, const float* __restrict__ bias,
    const float* __restrict__ gam, const float* __restrict__ bet,
    float* __restrict__ zv) {
    constexpr int F = 64;  // float4 per row (M = 256)
    __shared__ float4 sWe[16 * F];
    __shared__ float4 sAtt[F];
    __shared__ float sMean[16];
    __shared__ float4 sAgg[4][32];  // head-1 agg per node-in-block
    for (int i = threadIdx.x; i < 16 * F; i += blockDim.x)
        sWe[i] = ((const float4*)We)[i];
    for (int i = threadIdx.x; i < F; i += blockDim.x)
        sAtt[i] = ((const float4*)att)[i];
    if (threadIdx.x < 16) sMean[threadIdx.x] = easum[threadIdx.x] * invE;
    __syncthreads();

    const int gwarp = (blockIdx.x * blockDim.x + threadIdx.x) >> 5;
    const int lane = threadIdx.x & 31;
    const int t = gwarp & 1;          // head
    const int d = gwarp >> 1;         // node
    const int nib = (threadIdx.x >> 5) >> 1;  // node-in-block 0..3
    const int f = t * 32 + lane;      // this head's float4 column for this lane
    const float4* xl4 = (const float4*)xl;
    const float4* xr4 = (const float4*)xr;

    float4 agg = make_float4(0.f, 0.f, 0.f, 0.f);
    bool valid = (d < N_NODES);
    if (valid) {
        int beg = rowptr[d], end = rowptr[d + 1];
        float4 xrr = xr4[(size_t)d * F + f];
        float4 num = make_float4(0.f, 0.f, 0.f, 0.f);
        float den = 0.f;
        float4 a4 = sAtt[f];

        for (int p = beg; p < end; p += L1_EP) {
            int ne = end - p;
            if (ne > L1_EP) ne = L1_EP;
            int sidx[L1_EP];
            float eav[L1_EP];
#pragma unroll
            for (int e = 0; e < L1_EP; e++) {
                int idx = p + (e < ne ? e : ne - 1);
                sidx[e] = csr_src[idx];
                int eid = csr_eid[idx];
                bool lp = eid >= N_EDGES;
                eav[e] = (lane < 16)
                             ? (lp ? sMean[lane] : ea[(size_t)eid * 16 + lane])
                             : 0.f;
            }
            float4 xlv[L1_EP], eev[L1_EP];
#pragma unroll
            for (int e = 0; e < L1_EP; e++) {
                xlv[e] = xl4[(size_t)sidx[e] * F + f];
                eev[e] = make_float4(0.f, 0.f, 0.f, 0.f);
            }
#pragma unroll
            for (int k = 0; k < 16; k++) {
                float4 w = sWe[k * F + f];  // one load for EP edges
#pragma unroll
                for (int e = 0; e < L1_EP; e++) {
                    float ek = __shfl_sync(0xffffffffu, eav[e], k);
                    eev[e].x = fmaf(ek, w.x, eev[e].x);
                    eev[e].y = fmaf(ek, w.y, eev[e].y);
                    eev[e].z = fmaf(ek, w.z, eev[e].z);
                    eev[e].w = fmaf(ek, w.w, eev[e].w);
                }
            }
#pragma unroll
            for (int e = 0; e < L1_EP; e++) {
                float mx = xlv[e].x + xrr.x + eev[e].x;
                float my = xlv[e].y + xrr.y + eev[e].y;
                float mz = xlv[e].z + xrr.z + eev[e].z;
                float mw = xlv[e].w + xrr.w + eev[e].w;
                mx = mx > 0.f ? mx : 0.2f * mx;
                my = my > 0.f ? my : 0.2f * my;
                mz = mz > 0.f ? mz : 0.2f * mz;
                mw = mw > 0.f ? mw : 0.2f * mw;
                float sc = fmaf(mx, a4.x, fmaf(my, a4.y, fmaf(mz, a4.z, mw * a4.w)));
#pragma unroll
                for (int o = 16; o > 0; o >>= 1)
                    sc += __shfl_xor_sync(0xffffffffu, sc, o);
                if (e < ne) {
                    float exv = expf(sc);
                    den += exv;
                    num.x = fmaf(exv, xlv[e].x, num.x);
                    num.y = fmaf(exv, xlv[e].y, num.y);
                    num.z = fmaf(exv, xlv[e].z, num.z);
                    num.w = fmaf(exv, xlv[e].w, num.w);
                }
            }
        }
        float inv = 1.f / (den + 1e-16f);
        agg = make_float4(num.x * inv, num.y * inv, num.z * inv, num.w * inv);
    }
    if (t == 1) sAgg[nib][lane] = agg;
    __syncthreads();
    if (t == 0 && valid) {
        float4 a1 = sAgg[nib][lane];
        const float4 b4 = ((const float4*)bias)[lane];
        float v4[4];
        v4[0] = 0.5f * (agg.x + a1.x) + b4.x;
        v4[1] = 0.5f * (agg.y + a1.y) + b4.y;
        v4[2] = 0.5f * (agg.z + a1.z) + b4.z;
        v4[3] = 0.5f * (agg.w + a1.w) + b4.w;
        float s = v4[0] + v4[1] + v4[2] + v4[3];
#pragma unroll
        for (int o = 16; o > 0; o >>= 1) s += __shfl_xor_sync(0xffffffffu, s, o);
        float mu = s * (1.f / 128.f);
        float vs = 0.f;
#pragma unroll
        for (int q = 0; q < 4; q++) {
            float dd = v4[q] - mu;
            vs = fmaf(dd, dd, vs);
        }
#pragma unroll
        for (int o = 16; o > 0; o >>= 1) vs += __shfl_xor_sync(0xffffffffu, vs, o);
        float rstd = rsqrtf(vs * (1.f / 128.f) + 1e-5f);
        const float4 g4 = ((const float4*)gam)[lane];
        const float4 be4 = ((const float4*)bet)[lane];
        float gg[4] = {g4.x, g4.y, g4.z, g4.w};
        float ee2[4] = {be4.x, be4.y, be4.z, be4.w};
        float o4[4];
#pragma unroll
        for (int q = 0; q < 4; q++) {
            float o = (v4[q] - mu) * rstd * gg[q] + ee2[q];
            o4[q] = o > 0.f ? o : expm1f(o);
        }
        ((float4*)zv)[(size_t)d * 32 + lane] = make_float4(o4[0], o4[1], o4[2], o4[3]);
    }
}

// ---------------- fused single-pass GATv2 (heads=1), edge-batched ----------------
template <int HEADS, int EP>
__global__ __launch_bounds__(256) void gat_fused_b(
    const int* __restrict__ rowptr, const int* __restrict__ csr_src,
    const int* __restrict__ csr_eid, const float* __restrict__ ea,
    const float* __restrict__ We, const float* __restrict__ easum, float invE,
    const float* __restrict__ xl, const float* __restrict__ xr,
    const float* __restrict__ att, const float* __restrict__ bias,
    const float* __restrict__ gam, const float* __restrict__ bet,
    float* __restrict__ zv) {
    constexpr int M = HEADS * 128;
    constexpr int F = M / 4;  // float4 per row
    __shared__ float4 sWe[16 * F];
    __shared__ float4 sAtt[F];
    __shared__ float sMean[16];
    for (int i = threadIdx.x; i < 16 * F; i += blockDim.x)
        sWe[i] = ((const float4*)We)[i];
    for (int i = threadIdx.x; i < F; i += blockDim.x)
        sAtt[i] = ((const float4*)att)[i];
    if (threadIdx.x < 16) sMean[threadIdx.x] = easum[threadIdx.x] * invE;
    __syncthreads();

    int warp = (blockIdx.x * blockDim.x + threadIdx.x) >> 5;
    int lane = threadIdx.x & 31;
    if (warp >= N_NODES) return;
    int d = warp;
    int beg = rowptr[d], end = rowptr[d + 1];
    const float4* xl4 = (const float4*)xl;
    const float4* xr4 = (const float4*)xr;

    float4 xrr[HEADS];
#pragma unroll
    for (int t = 0; t < HEADS; t++) xrr[t] = xr4[(size_t)d * F + t * 32 + lane];

    float4 num[HEADS];
    float den[HEADS];
#pragma unroll
    for (int t = 0; t < HEADS; t++) {
        num[t] = make_float4(0.f, 0.f, 0.f, 0.f);
        den[t] = 0.f;
    }

    for (int p = beg; p < end; p += EP) {
        int ne = end - p;
        if (ne > EP) ne = EP;
        int sidx[EP];
        float eav[EP];
#pragma unroll
        for (int e = 0; e < EP; e++) {
            int idx = p + (e < ne ? e : ne - 1);  // clamp; masked below
            sidx[e] = csr_src[idx];
            int eid = csr_eid[idx];
            bool lp = eid >= N_EDGES;
            eav[e] = (lane < 16)
                         ? (lp ? sMean[lane] : ea[(size_t)eid * 16 + lane])
                         : 0.f;
        }
#pragma unroll
        for (int t = 0; t < HEADS; t++) {
            float4 xlv[EP], eev[EP];
#pragma unroll
            for (int e = 0; e < EP; e++) {
                xlv[e] = xl4[(size_t)sidx[e] * F + t * 32 + lane];
                eev[e] = make_float4(0.f, 0.f, 0.f, 0.f);
            }
#pragma unroll
            for (int k = 0; k < 16; k++) {
                float4 w = sWe[k * F + t * 32 + lane];  // ONE load for EP edges
#pragma unroll
                for (int e = 0; e < EP; e++) {
                    float ek = __shfl_sync(0xffffffffu, eav[e], k);
                    eev[e].x = fmaf(ek, w.x, eev[e].x);
                    eev[e].y = fmaf(ek, w.y, eev[e].y);
                    eev[e].z = fmaf(ek, w.z, eev[e].z);
                    eev[e].w = fmaf(ek, w.w, eev[e].w);
                }
            }
            float4 a4 = sAtt[t * 32 + lane];
#pragma unroll
            for (int e = 0; e < EP; e++) {
                float mx = xlv[e].x + xrr[t].x + eev[e].x;
                float my = xlv[e].y + xrr[t].y + eev[e].y;
                float mz = xlv[e].z + xrr[t].z + eev[e].z;
                float mw = xlv[e].w + xrr[t].w + eev[e].w;
                mx = mx > 0.f ? mx : 0.2f * mx;
                my = my > 0.f ? my : 0.2f * my;
                mz = mz > 0.f ? mz : 0.2f * mz;
                mw = mw > 0.f ? mw : 0.2f * mw;
                float sc = fmaf(mx, a4.x, fmaf(my, a4.y, fmaf(mz, a4.z, mw * a4.w)));
#pragma unroll
                for (int o = 16; o > 0; o >>= 1)
                    sc += __shfl_xor_sync(0xffffffffu, sc, o);
                if (e < ne) {
                    float exv = expf(sc);
                    den[t] += exv;
                    num[t].x = fmaf(exv, xlv[e].x, num[t].x);
                    num[t].y = fmaf(exv, xlv[e].y, num[t].y);
                    num[t].z = fmaf(exv, xlv[e].z, num[t].z);
                    num[t].w = fmaf(exv, xlv[e].w, num[t].w);
                }
            }
        }
    }
    float inv[HEADS];
#pragma unroll
    for (int t = 0; t < HEADS; t++) inv[t] = 1.f / (den[t] + 1e-16f);

    float v4[4];
    {
        const float4 b4 = ((const float4*)bias)[lane];
        float n0[4] = {num[0].x, num[0].y, num[0].z, num[0].w};
        float bb[4] = {b4.x, b4.y, b4.z, b4.w};
        float n1[4];
        if (HEADS == 2) { n1[0] = num[1].x; n1[1] = num[1].y; n1[2] = num[1].z; n1[3] = num[1].w; }
#pragma unroll
        for (int q = 0; q < 4; q++) {
            float a = n0[q] * inv[0];
            if (HEADS == 2) a = 0.5f * (a + n1[q] * inv[1]);
            v4[q] = a + bb[q];
        }
    }
    float s = v4[0] + v4[1] + v4[2] + v4[3];
#pragma unroll
    for (int o = 16; o > 0; o >>= 1) s += __shfl_xor_sync(0xffffffffu, s, o);
    float mu = s * (1.f / 128.f);
    float vs = 0.f;
#pragma unroll
    for (int q = 0; q < 4; q++) {
        float dd = v4[q] - mu;
        vs = fmaf(dd, dd, vs);
    }
#pragma unroll
    for (int o = 16; o > 0; o >>= 1) vs += __shfl_xor_sync(0xffffffffu, vs, o);
    float rstd = rsqrtf(vs * (1.f / 128.f) + 1e-5f);
    const float4 g4 = ((const float4*)gam)[lane];
    const float4 be4 = ((const float4*)bet)[lane];
    float gg[4] = {g4.x, g4.y, g4.z, g4.w};
    float ee2[4] = {be4.x, be4.y, be4.z, be4.w};
    float o4[4];
#pragma unroll
    for (int q = 0; q < 4; q++) {
        float o = (v4[q] - mu) * rstd * gg[q] + ee2[q];
        o4[q] = o > 0.f ? o : expm1f(o);
    }
    ((float4*)zv)[(size_t)d * 32 + lane] = make_float4(o4[0], o4[1], o4[2], o4[3]);
}

// ---------------- GRU (h_prev = 0) ----------------
__global__ void gru_kernel(const float* __restrict__ gi, const float* __restrict__ bhh,
                           float* __restrict__ h) {
    int idx = blockIdx.x * blockDim.x + threadIdx.x;
    if (idx >= N_NODES * 128) return;
    int n = idx >> 7, c = idx & 127;
    const float* g = gi + (size_t)n * 384;
    float r = 1.f / (1.f + expf(-(g[c] + bhh[c])));
    float u = 1.f / (1.f + expf(-(g[128 + c] + bhh[128 + c])));
    float ng = tanhf(g[256 + c] + r * bhh[256 + c]);
    h[idx] = (1.f - u) * ng;
}

// ---------------- classifier v7: 128 edges/block, tc stage 2, prepacked Wc2 ----------
#define C6_SO1_SLAB 1032  // 128*8 + 8
#define C6_SW2_SLAB 520   // 64*8 + 8
#define C6_SO1_WORDS (16 * C6_SO1_SLAB)
#define C6_SW2_WORDS (16 * C6_SW2_SLAB)
#define C6_SEA_WORDS (128 * 16)
#define C6_PART_WORDS 256
#define C6_SMEM_WORDS (C6_SO1_WORDS + C6_SW2_WORDS + C6_SEA_WORDS + C6_PART_WORDS)
__global__ __launch_bounds__(256) void classifier7(
    const float* __restrict__ A, const float* __restrict__ B,
    const int* __restrict__ src, const int* __restrict__ dst,
    const float* __restrict__ ea, const float* __restrict__ Wc1c,
    const uint32_t* __restrict__ wc2p, const float* __restrict__ bc2,
    const float* __restrict__ Wc3, const float* __restrict__ bc3,
    float* __restrict__ out, int E) {
    extern __shared__ uint32_t smu[];
    uint32_t* sO1 = smu;                                  // packed o1 [16][128e][8]
    uint32_t* sW2 = smu + C6_SO1_WORDS;                   // packed Wc2 [16][64n][8]
    float* sEA = (float*)(smu + C6_SO1_WORDS + C6_SW2_WORDS);
    float* sPart = (float*)(smu + C6_SO1_WORDS + C6_SW2_WORDS + C6_SEA_WORDS);
    __shared__ int sSrc[128], sDst[128];
    const int tid = threadIdx.x;
    const int e0 = blockIdx.x * 128;

    // copy prepacked Wc2 (coalesced uint4, no remap)
    for (int w = tid * 4; w < 8192; w += 1024) {
        int g = w >> 9, rem = w & 511;
        *(uint4*)&sW2[g * C6_SW2_SLAB + rem] = *(const uint4*)&wc2p[w];
    }
    for (int idx = tid; idx < 128 * 16 / 4; idx += 256)
        ((float4*)sEA)[idx] = (e0 * 4 + idx < E * 4)
                                  ? ((const float4*)ea)[(size_t)e0 * 4 + idx]
                                  : make_float4(0.f, 0.f, 0.f, 0.f);
    if (tid < 128) {
        int ge = e0 + tid;
        sSrc[tid] = (ge < E) ? src[ge] : 0;
        sDst[tid] = (ge < E) ? dst[ge] : 0;
    }
    __syncthreads();

    // ---- stage 1 ----
    {
        const int col = tid & 127;
        const int half = tid >> 7;
        const int g = col >> 3;
        const int s = ((col & 3) << 1) | ((col >> 2) & 1);
        float w1c[16];
#pragma unroll
        for (int k = 0; k < 16; k++) w1c[k] = Wc1c[k * 128 + col];
        for (int i = 0; i < 64; i++) {
            int e = half * 64 + i;
            int ss = sSrc[e], dd = sDst[e];
            float acc = A[(size_t)ss * 128 + col] + B[(size_t)dd * 128 + col];
            const float4* ea4 = (const float4*)&sEA[e * 16];
#pragma unroll
            for (int k4 = 0; k4 < 4; k4++) {
                float4 v = ea4[k4];
                acc = fmaf(v.x, w1c[k4 * 4 + 0], acc);
                acc = fmaf(v.y, w1c[k4 * 4 + 1], acc);
                acc = fmaf(v.z, w1c[k4 * 4 + 2], acc);
                acc = fmaf(v.w, w1c[k4 * 4 + 3], acc);
            }
            sO1[g * C6_SO1_SLAB + e * 8 + s] = f2tf32(fmaxf(acc, 0.f));
        }
    }
    __syncthreads();

    // ---- stage 2: tf32 mma ----
    {
        const int warp = tid >> 5, lane = tid & 31;
        const int lk = lane & 3, lr = lane >> 2;
        const int eg = warp >> 1;
        const int cg = warp & 1;
        float acc[2][4][4];
#pragma unroll
        for (int mt = 0; mt < 2; mt++)
#pragma unroll
            for (int nt = 0; nt < 4; nt++)
#pragma unroll
                for (int i = 0; i < 4; i++) acc[mt][nt][i] = 0.f;

#pragma unroll
        for (int g = 0; g < 16; g++) {
            uint32_t af[2][4];
#pragma unroll
            for (int mt = 0; mt < 2; mt++) {
                int e = eg * 32 + mt * 16 + lr;
                uint2 p0 = *(const uint2*)&sO1[g * C6_SO1_SLAB + e * 8 + lk * 2];
                uint2 p1 = *(const uint2*)&sO1[g * C6_SO1_SLAB + (e + 8) * 8 + lk * 2];
                af[mt][0] = p0.x; af[mt][2] = p0.y;
                af[mt][1] = p1.x; af[mt][3] = p1.y;
            }
#pragma unroll
            for (int nt = 0; nt < 4; nt++) {
                int n = cg * 32 + nt * 8 + lr;
                uint2 q = *(const uint2*)&sW2[g * C6_SW2_SLAB + n * 8 + lk * 2];
                uint32_t bf[2] = {q.x, q.y};
                mma_tf32(acc[0][nt], af[0], bf);
                mma_tf32(acc[1][nt], af[1], bf);
            }
        }

        // ---- fused stage 3 ----
        float p[2][2];
#pragma unroll
        for (int mt = 0; mt < 2; mt++) { p[mt][0] = 0.f; p[mt][1] = 0.f; }
#pragma unroll
        for (int nt = 0; nt < 4; nt++) {
            int c = cg * 32 + nt * 8 + lk * 2;
            float bA = bc2[c], bB = bc2[c + 1];
            float wA = Wc3[c], wB = Wc3[c + 1];
#pragma unroll
            for (int mt = 0; mt < 2; mt++) {
                p[mt][0] = fmaf(fmaxf(acc[mt][nt][0] + bA, 0.f), wA, p[mt][0]);
                p[mt][0] = fmaf(fmaxf(acc[mt][nt][1] + bB, 0.f), wB, p[mt][0]);
                p[mt][1] = fmaf(fmaxf(acc[mt][nt][2] + bA, 0.f), wA, p[mt][1]);
                p[mt][1] = fmaf(fmaxf(acc[mt][nt][3] + bB, 0.f), wB, p[mt][1]);
            }
        }
#pragma unroll
        for (int mt = 0; mt < 2; mt++)
#pragma unroll
            for (int rh = 0; rh < 2; rh++) {
                p[mt][rh] += __shfl_xor_sync(0xffffffffu, p[mt][rh], 1);
                p[mt][rh] += __shfl_xor_sync(0xffffffffu, p[mt][rh], 2);
            }
        if (lk == 0) {
#pragma unroll
            for (int mt = 0; mt < 2; mt++) {
                int r = eg * 32 + mt * 16 + lr;
                sPart[cg * 128 + r] = p[mt][0];
                sPart[cg * 128 + r + 8] = p[mt][1];
            }
        }
    }
    __syncthreads();
    if (tid < 128) {
        int ge = e0 + tid;
        if (ge < E) out[ge] = sPart[tid] + sPart[128 + tid] + bc3[0];
    }
}

// ---------------- launch ----------------
extern "C" void kernel_launch(void* const* d_in, const int* in_sizes, int n_in,
                              void* d_out, int out_size) {
    const float* x   = (const float*)d_in[0];
    const int*   ei  = (const int*)d_in[1];
    const float* ea  = (const float*)d_in[2];
    const float* Wl1 = (const float*)d_in[3];
    const float* bl1 = (const float*)d_in[4];
    const float* Wr1 = (const float*)d_in[5];
    const float* br1 = (const float*)d_in[6];
    const float* We1 = (const float*)d_in[7];
    const float* att1 = (const float*)d_in[8];
    const float* bias1 = (const float*)d_in[9];
    const float* g1 = (const float*)d_in[10];
    const float* be1 = (const float*)d_in[11];
    const float* Wl2 = (const float*)d_in[12];
    const float* bl2 = (const float*)d_in[13];
    const float* Wr2 = (const float*)d_in[14];
    const float* br2 = (const float*)d_in[15];
    const float* We2 = (const float*)d_in[16];
    const float* att2 = (const float*)d_in[17];
    const float* bias2 = (const float*)d_in[18];
    const float* g2 = (const float*)d_in[19];
    const float* be2 = (const float*)d_in[20];
    const float* W_ih = (const float*)d_in[21];
    /* W_hh d_in[22] unused: h_prev == 0 */
    const float* b_ih = (const float*)d_in[23];
    const float* b_hh = (const float*)d_in[24];
    const float* Wc1 = (const float*)d_in[25];
    const float* bc1 = (const float*)d_in[26];
    const float* Wc2 = (const float*)d_in[27];
    const float* bc2 = (const float*)d_in[28];
    const float* Wc3 = (const float*)d_in[29];
    const float* bc3 = (const float*)d_in[30];
    float* out = (float*)d_out;

    const int* src = ei;
    const int* dst = ei + N_EDGES;

    float *xl, *xr, *zv1, *zv2, *gi, *h, *Wt, *easum;
    uint32_t* wc2p;
    int *deg, *fill, *rowptr, *csr_src, *csr_eid;
    cudaGetSymbolAddress((void**)&xl, g_xl);
    cudaGetSymbolAddress((void**)&xr, g_xr);
    cudaGetSymbolAddress((void**)&zv1, g_zv1);
    cudaGetSymbolAddress((void**)&zv2, g_zv2);
    cudaGetSymbolAddress((void**)&gi, g_gi);
    cudaGetSymbolAddress((void**)&h, g_h);
    cudaGetSymbolAddress((void**)&Wt, g_Wt);
    cudaGetSymbolAddress((void**)&easum, g_easum);
    cudaGetSymbolAddress((void**)&wc2p, g_wc2p);
    cudaGetSymbolAddress((void**)&deg, g_deg);
    cudaGetSymbolAddress((void**)&fill, g_fill);
    cudaGetSymbolAddress((void**)&rowptr, g_rowptr);
    cudaGetSymbolAddress((void**)&csr_src, g_csr_src);
    cudaGetSymbolAddress((void**)&csr_eid, g_csr_eid);

    const float invE = 1.f / (float)N_EDGES;

    // one-time setup on the first (uncaptured) call: streams, events, smem attr
    static cudaStream_t s1 = nullptr, s2 = nullptr;
    static cudaEvent_t ev[3];
    if (!s1) {
        cudaFuncSetAttribute(classifier7, cudaFuncAttributeMaxDynamicSharedMemorySize,
                             C6_SMEM_WORDS * sizeof(uint32_t));
        cudaStreamCreateWithFlags(&s1, cudaStreamNonBlocking);
        cudaStreamCreateWithFlags(&s2, cudaStreamNonBlocking);
        for (int i = 0; i < 3; i++) cudaEventCreateWithFlags(&ev[i], cudaEventDisableTiming);
    }

    const int NB = (N_NODES + 127) / 128;  // 157 row-blocks

    // ---- fork: s1 = CSR build chain, s2 = transpose + Wc2 pack, s0 = easum + xl1|xr1 ----
    cudaEventRecord(ev[0], 0);
    cudaStreamWaitEvent(s1, ev[0], 0);
    cudaStreamWaitEvent(s2, ev[0], 0);

    // s1: CSR chain
    zero2_i<<<(N_NODES + 255) / 256, 256, 0, s1>>>(deg, fill, N_NODES);
    deg_count<<<(N_EDGES + 255) / 256, 256, 0, s1>>>(dst, deg);
    scan_kernel<<<1, 1024, 0, s1>>>(deg, rowptr);
    scatter_kernel<<<(N_ITEMS + 255) / 256, 256, 0, s1>>>(src, dst, rowptr, fill,
                                                          csr_src, csr_eid);
    cudaEventRecord(ev[1], s1);

    // s2: transpose + Wc2 pack
    transpose_wih<<<(384 * 128 + 255) / 256, 256, 0, s2>>>(W_ih, Wt);
    pack_wc2<<<32, 256, 0, s2>>>(Wc2, wc2p);
    cudaEventRecord(ev[2], s2);

    // s0: edge-attr mean + fused xl1|xr1 dual GEMM (628 blocks)
    zero_f<<<1, 32>>>(easum, 16);
    ea_colsum4<<<256, 256>>>(ea, easum);
    {
        dim3 grid(4, NB);
        gemm_tc2<<<grid, 256>>>(x, Wl1, bl1, xl, Wr1, br1, xr, N_NODES, 128, 256, 2);
    }

    // ---- join, GAT layer 1 (head-split, EP=4) ----
    cudaStreamWaitEvent(0, ev[1], 0);
    cudaStreamWaitEvent(0, ev[2], 0);
    gat_l1_hsplit<<<(N_NODES * 2 + 7) / 8, 256>>>(rowptr, csr_src, csr_eid, ea, We1,
                                                  easum, invE, xl, xr, att1, bias1,
                                                  g1, be1, zv1);

    // ---- layer 2: fused xl2|xr2 dual GEMM (314 blocks) ----
    {
        dim3 grid(2, NB);
        gemm_tc2<<<grid, 256>>>(zv1, Wl2, bl2, xl, Wr2, br2, xr, N_NODES, 128, 128, 1);
    }
    gat_fused_b<1, 4><<<(N_NODES + 7) / 8, 256>>>(rowptr, csr_src, csr_eid, ea, We2,
                                                  easum, invE, xl, xr, att2, bias2,
                                                  g2, be2, zv2);

    // ---- GRU (h_prev = 0) ----
    {
        dim3 grid(3, NB);
        gemm_tc2<<<grid, 256>>>(zv2, Wt, b_ih, gi,
                                (const float*)nullptr, (const float*)nullptr,
                                (float*)nullptr, N_NODES, 128, 384, 3);
    }
    gru_kernel<<<(N_NODES * 128 + 255) / 256, 256>>>(gi, b_hh, h);

    // ---- classifier: fused A|B dual GEMM, then fused edge MLP (tensor-core) ----
    float* Amat = xl;
    float* Bmat = xl + (size_t)N_NODES * 128;
    {
        dim3 grid(2, NB);
        gemm_tc2<<<grid, 256>>>(h, Wc1, bc1, Amat,
                                Wc1 + 128 * 128, (const float*)nullptr, Bmat,
                                N_NODES, 128, 128, 1);
    }
    classifier7<<<(N_EDGES + 127) / 128, 256, C6_SMEM_WORDS * sizeof(uint32_t)>>>(
        Amat, Bmat, src, dst, ea, Wc1 + 256 * 128, wc2p, bc2, Wc3, bc3, out, N_EDGES);
}

// round 15
// speedup vs baseline: 1.0713x; 1.0713x over previous
#include <cuda_runtime.h>
#include <math.h>
#include <stdint.h>

#define N_NODES 20000
#define N_EDGES 320000
#define N_ITEMS (N_EDGES + N_NODES)

// ---------------- scratch (device globals; no allocs allowed) ----------------
__device__ float g_xl[N_NODES * 256];
__device__ float g_xr[N_NODES * 256];
__device__ float g_zv1[N_NODES * 128];
__device__ float g_zv2[N_NODES * 128];
__device__ float g_gi[N_NODES * 384];
__device__ float g_h[N_NODES * 128];
__device__ float g_Wt[128 * 384];
__device__ float g_easum[16];
__device__ uint32_t g_wc2p[8192];
__device__ int g_deg[N_NODES];
__device__ int g_fill[N_NODES];
__device__ int g_rowptr[N_NODES + 1];
__device__ int g_csr_src[N_ITEMS];
__device__ int g_csr_eid[N_ITEMS];

// ---------------- utility kernels ----------------
__global__ void zero_f(float* p, int n) {
    int i = blockIdx.x * blockDim.x + threadIdx.x;
    if (i < n) p[i] = 0.f;
}
__global__ void zero2_i(int* p0, int* p1, int n) {
    int i = blockIdx.x * blockDim.x + threadIdx.x;
    if (i < n) { p0[i] = 0; p1[i] = 0; }
}

__global__ void ea_colsum4(const float* __restrict__ ea, float* easum) {
    __shared__ float sh[16];
    if (threadIdx.x < 16) sh[threadIdx.x] = 0.f;
    __syncthreads();
    int g = blockIdx.x * blockDim.x + threadIdx.x;
    int stride = gridDim.x * blockDim.x;
    int q = g & 3;
    int slot = g >> 2;
    int ns = stride >> 2;
    float4 acc = make_float4(0.f, 0.f, 0.f, 0.f);
    for (int e = slot; e < N_EDGES; e += ns) {
        float4 v = *(const float4*)&ea[(size_t)e * 16 + q * 4];
        acc.x += v.x; acc.y += v.y; acc.z += v.z; acc.w += v.w;
    }
    atomicAdd(&sh[q * 4 + 0], acc.x);
    atomicAdd(&sh[q * 4 + 1], acc.y);
    atomicAdd(&sh[q * 4 + 2], acc.z);
    atomicAdd(&sh[q * 4 + 3], acc.w);
    __syncthreads();
    if (threadIdx.x < 16) atomicAdd(&easum[threadIdx.x], sh[threadIdx.x]);
}

__global__ void transpose_wih(const float* __restrict__ W, float* __restrict__ Wt) {
    int i = blockIdx.x * blockDim.x + threadIdx.x;
    if (i < 384 * 128) {
        int j = i / 128, k = i % 128;
        Wt[k * 384 + j] = W[i];
    }
}

// ---------------- tf32 helpers ----------------
__device__ __forceinline__ uint32_t f2tf32(float x) {
    uint32_t r;
    asm("cvt.rna.tf32.f32 %0, %1;" : "=r"(r) : "f"(x));
    return r;
}
__device__ __forceinline__ void mma_tf32(float* c, const uint32_t* a, const uint32_t* b) {
    asm volatile(
        "mma.sync.aligned.m16n8k8.row.col.f32.tf32.tf32.f32 "
        "{%0,%1,%2,%3}, {%4,%5,%6,%7}, {%8,%9}, {%0,%1,%2,%3};"
        : "+f"(c[0]), "+f"(c[1]), "+f"(c[2]), "+f"(c[3])
        : "r"(a[0]), "r"(a[1]), "r"(a[2]), "r"(a[3]), "r"(b[0]), "r"(b[1]));
}

// pack Wc2 [128k][64n] into tf32 words laid out [g=k/8][n][s], s=((k&3)<<1)|((k>>2)&1)
__global__ void pack_wc2(const float* __restrict__ Wc2, uint32_t* __restrict__ wc2p) {
    int w = blockIdx.x * blockDim.x + threadIdx.x;
    if (w < 8192) {
        int g = w >> 9, rem = w & 511, n = rem >> 3, s = rem & 7;
        int k = g * 8 + (s & 1) * 4 + (s >> 1);
        wc2p[w] = f2tf32(Wc2[k * 64 + n]);
    }
}

// ---------------- CSR build ----------------
__global__ void deg_count(const int* __restrict__ dst, int* __restrict__ deg) {
    int i = blockIdx.x * blockDim.x + threadIdx.x;
    if (i < N_EDGES) atomicAdd(&deg[dst[i]], 1);
}

__global__ void scan_kernel(const int* __restrict__ deg, int* __restrict__ rowptr) {
    __shared__ int ssum[1024];
    const int CH = 20;
    int t = threadIdx.x;
    int base = t * CH;
    int s = 0;
    for (int i = 0; i < CH; i++) {
        int node = base + i;
        if (node < N_NODES) s += deg[node] + 1;
    }
    ssum[t] = s;
    __syncthreads();
    for (int off = 1; off < 1024; off <<= 1) {
        int v = (t >= off) ? ssum[t - off] : 0;
        __syncthreads();
        ssum[t] += v;
        __syncthreads();
    }
    int run = (t == 0) ? 0 : ssum[t - 1];
    for (int i = 0; i < CH; i++) {
        int node = base + i;
        if (node < N_NODES) {
            rowptr[node] = run;
            run += deg[node] + 1;
        } else if (node == N_NODES) {
            rowptr[node] = run;
        }
    }
}

__global__ void scatter_kernel(const int* __restrict__ src, const int* __restrict__ dst,
                               const int* __restrict__ rowptr, int* __restrict__ fill,
                               int* __restrict__ csr_src, int* __restrict__ csr_eid) {
    int i = blockIdx.x * blockDim.x + threadIdx.x;
    if (i >= N_ITEMS) return;
    int s, d;
    if (i < N_EDGES) { s = src[i]; d = dst[i]; }
    else { s = i - N_EDGES; d = s; }
    int pos = rowptr[d] + atomicAdd(&fill[d], 1);
    csr_src[pos] = s;
    csr_eid[pos] = i;
}

// ---------------- tf32 tensor-core GEMM, dual-output, reg-prefetch pipelined ----------
__global__ __launch_bounds__(256) void gemm_tc2(
    const float* __restrict__ A,
    const float* __restrict__ B0, const float* __restrict__ bias0, float* __restrict__ C0,
    const float* __restrict__ B1, const float* __restrict__ bias1, float* __restrict__ C1,
    int n, int K, int M, int gx0) {
    __shared__ uint32_t As[16][132];
    __shared__ uint32_t Bs[16][132];
    const int tid = threadIdx.x;
    const int warp = tid >> 5, lane = tid & 31;
    const int warpM = (warp >> 1) * 32;
    const int warpN = (warp & 1) * 64;
    int bx = blockIdx.x;
    const float* B;
    const float* bias;
    float* C;
    if (bx < gx0) { B = B0; bias = bias0; C = C0; }
    else { bx -= gx0; B = B1; bias = bias1; C = C1; }
    const int row0 = blockIdx.y * 128, col0 = bx * 128;
    const int lk = lane & 3;
    const int lr = lane >> 2;

    int arow[2], aq[2], brow[2], bq[2];
#pragma unroll
    for (int i = 0; i < 2; i++) {
        int idx = tid * 2 + i;
        arow[i] = idx >> 2;
        aq[i] = idx & 3;
        brow[i] = idx >> 5;
        bq[i] = idx & 31;
    }

    float acc[2][8][4] = {};
    float4 pa[2], pb[2];

#pragma unroll
    for (int i = 0; i < 2; i++) {
        int r = row0 + arow[i];
        pa[i] = (r < n) ? *(const float4*)&A[(size_t)r * K + aq[i] * 4]
                        : make_float4(0.f, 0.f, 0.f, 0.f);
        pb[i] = *(const float4*)&B[(size_t)brow[i] * M + col0 + bq[i] * 4];
    }

    for (int k0 = 0; k0 < K; k0 += 16) {
#pragma unroll
        for (int i = 0; i < 2; i++) {
            As[aq[i] * 4 + 0][arow[i]] = f2tf32(pa[i].x);
            As[aq[i] * 4 + 1][arow[i]] = f2tf32(pa[i].y);
            As[aq[i] * 4 + 2][arow[i]] = f2tf32(pa[i].z);
            As[aq[i] * 4 + 3][arow[i]] = f2tf32(pa[i].w);
            uint4 tv;
            tv.x = f2tf32(pb[i].x); tv.y = f2tf32(pb[i].y);
            tv.z = f2tf32(pb[i].z); tv.w = f2tf32(pb[i].w);
            *(uint4*)&Bs[brow[i]][bq[i] * 4] = tv;
        }
        __syncthreads();
        if (k0 + 16 < K) {
#pragma unroll
            for (int i = 0; i < 2; i++) {
                int r = row0 + arow[i];
                pa[i] = (r < n) ? *(const float4*)&A[(size_t)r * K + k0 + 16 + aq[i] * 4]
                                : make_float4(0.f, 0.f, 0.f, 0.f);
                pb[i] = *(const float4*)&B[(size_t)(k0 + 16 + brow[i]) * M + col0 + bq[i] * 4];
            }
        }
#pragma unroll
        for (int ks = 0; ks < 16; ks += 8) {
            uint32_t af[2][4];
#pragma unroll
            for (int mt = 0; mt < 2; mt++) {
                int m = warpM + mt * 16 + lr;
                af[mt][0] = As[ks + lk][m];
                af[mt][1] = As[ks + lk][m + 8];
                af[mt][2] = As[ks + lk + 4][m];
                af[mt][3] = As[ks + lk + 4][m + 8];
            }
            uint32_t bf[8][2];
#pragma unroll
            for (int nt = 0; nt < 8; nt++) {
                int nn = warpN + nt * 8 + lr;
                bf[nt][0] = Bs[ks + lk][nn];
                bf[nt][1] = Bs[ks + lk + 4][nn];
            }
#pragma unroll
            for (int mt = 0; mt < 2; mt++)
#pragma unroll
                for (int nt = 0; nt < 8; nt++) mma_tf32(acc[mt][nt], af[mt], bf[nt]);
        }
        __syncthreads();
    }
#pragma unroll
    for (int mt = 0; mt < 2; mt++) {
        int r0 = row0 + warpM + mt * 16 + lr;
        int r1 = r0 + 8;
#pragma unroll
        for (int nt = 0; nt < 8; nt++) {
            int c = col0 + warpN + nt * 8 + lk * 2;
            float b0 = bias ? bias[c] : 0.f;
            float b1 = bias ? bias[c + 1] : 0.f;
            if (r0 < n) {
                float2 v = make_float2(acc[mt][nt][0] + b0, acc[mt][nt][1] + b1);
                *(float2*)&C[(size_t)r0 * M + c] = v;
            }
            if (r1 < n) {
                float2 v = make_float2(acc[mt][nt][2] + b0, acc[mt][nt][3] + b1);
                *(float2*)&C[(size_t)r1 * M + c] = v;
            }
        }
    }
}

// ---------------- fused single-pass GATv2, edge-batched (EP edges share We loads) ----
template <int HEADS, int EP>
__global__ __launch_bounds__(256) void gat_fused_b(
    const int* __restrict__ rowptr, const int* __restrict__ csr_src,
    const int* __restrict__ csr_eid, const float* __restrict__ ea,
    const float* __restrict__ We, const float* __restrict__ easum, float invE,
    const float* __restrict__ xl, const float* __restrict__ xr,
    const float* __restrict__ att, const float* __restrict__ bias,
    const float* __restrict__ gam, const float* __restrict__ bet,
    float* __restrict__ zv) {
    constexpr int M = HEADS * 128;
    constexpr int F = M / 4;
    __shared__ float4 sWe[16 * F];
    __shared__ float4 sAtt[F];
    __shared__ float sMean[16];
    for (int i = threadIdx.x; i < 16 * F; i += blockDim.x)
        sWe[i] = ((const float4*)We)[i];
    for (int i = threadIdx.x; i < F; i += blockDim.x)
        sAtt[i] = ((const float4*)att)[i];
    if (threadIdx.x < 16) sMean[threadIdx.x] = easum[threadIdx.x] * invE;
    __syncthreads();

    int warp = (blockIdx.x * blockDim.x + threadIdx.x) >> 5;
    int lane = threadIdx.x & 31;
    if (warp >= N_NODES) return;
    int d = warp;
    int beg = rowptr[d], end = rowptr[d + 1];
    const float4* xl4 = (const float4*)xl;
    const float4* xr4 = (const float4*)xr;

    float4 xrr[HEADS];
#pragma unroll
    for (int t = 0; t < HEADS; t++) xrr[t] = xr4[(size_t)d * F + t * 32 + lane];

    float4 num[HEADS];
    float den[HEADS];
#pragma unroll
    for (int t = 0; t < HEADS; t++) {
        num[t] = make_float4(0.f, 0.f, 0.f, 0.f);
        den[t] = 0.f;
    }

    for (int p = beg; p < end; p += EP) {
        int ne = end - p;
        if (ne > EP) ne = EP;
        int sidx[EP];
        float eav[EP];
#pragma unroll
        for (int e = 0; e < EP; e++) {
            int idx = p + (e < ne ? e : ne - 1);
            sidx[e] = csr_src[idx];
            int eid = csr_eid[idx];
            bool lp = eid >= N_EDGES;
            eav[e] = (lane < 16)
                         ? (lp ? sMean[lane] : ea[(size_t)eid * 16 + lane])
                         : 0.f;
        }
#pragma unroll
        for (int t = 0; t < HEADS; t++) {
            float4 xlv[EP], eev[EP];
#pragma unroll
            for (int e = 0; e < EP; e++) {
                xlv[e] = xl4[(size_t)sidx[e] * F + t * 32 + lane];
                eev[e] = make_float4(0.f, 0.f, 0.f, 0.f);
            }
#pragma unroll
            for (int k = 0; k < 16; k++) {
                float4 w = sWe[k * F + t * 32 + lane];
#pragma unroll
                for (int e = 0; e < EP; e++) {
                    float ek = __shfl_sync(0xffffffffu, eav[e], k);
                    eev[e].x = fmaf(ek, w.x, eev[e].x);
                    eev[e].y = fmaf(ek, w.y, eev[e].y);
                    eev[e].z = fmaf(ek, w.z, eev[e].z);
                    eev[e].w = fmaf(ek, w.w, eev[e].w);
                }
            }
            float4 a4 = sAtt[t * 32 + lane];
#pragma unroll
            for (int e = 0; e < EP; e++) {
                float mx = xlv[e].x + xrr[t].x + eev[e].x;
                float my = xlv[e].y + xrr[t].y + eev[e].y;
                float mz = xlv[e].z + xrr[t].z + eev[e].z;
                float mw = xlv[e].w + xrr[t].w + eev[e].w;
                mx = mx > 0.f ? mx : 0.2f * mx;
                my = my > 0.f ? my : 0.2f * my;
                mz = mz > 0.f ? mz : 0.2f * mz;
                mw = mw > 0.f ? mw : 0.2f * mw;
                float sc = fmaf(mx, a4.x, fmaf(my, a4.y, fmaf(mz, a4.z, mw * a4.w)));
#pragma unroll
                for (int o = 16; o > 0; o >>= 1)
                    sc += __shfl_xor_sync(0xffffffffu, sc, o);
                if (e < ne) {
                    float exv = expf(sc);
                    den[t] += exv;
                    num[t].x = fmaf(exv, xlv[e].x, num[t].x);
                    num[t].y = fmaf(exv, xlv[e].y, num[t].y);
                    num[t].z = fmaf(exv, xlv[e].z, num[t].z);
                    num[t].w = fmaf(exv, xlv[e].w, num[t].w);
                }
            }
        }
    }
    float inv[HEADS];
#pragma unroll
    for (int t = 0; t < HEADS; t++) inv[t] = 1.f / (den[t] + 1e-16f);

    float v4[4];
    {
        const float4 b4 = ((const float4*)bias)[lane];
        float n0[4] = {num[0].x, num[0].y, num[0].z, num[0].w};
        float bb[4] = {b4.x, b4.y, b4.z, b4.w};
        float n1[4];
        if (HEADS == 2) { n1[0] = num[1].x; n1[1] = num[1].y; n1[2] = num[1].z; n1[3] = num[1].w; }
#pragma unroll
        for (int q = 0; q < 4; q++) {
            float a = n0[q] * inv[0];
            if (HEADS == 2) a = 0.5f * (a + n1[q] * inv[1]);
            v4[q] = a + bb[q];
        }
    }
    float s = v4[0] + v4[1] + v4[2] + v4[3];
#pragma unroll
    for (int o = 16; o > 0; o >>= 1) s += __shfl_xor_sync(0xffffffffu, s, o);
    float mu = s * (1.f / 128.f);
    float vs = 0.f;
#pragma unroll
    for (int q = 0; q < 4; q++) {
        float dd = v4[q] - mu;
        vs = fmaf(dd, dd, vs);
    }
#pragma unroll
    for (int o = 16; o > 0; o >>= 1) vs += __shfl_xor_sync(0xffffffffu, vs, o);
    float rstd = rsqrtf(vs * (1.f / 128.f) + 1e-5f);
    const float4 g4 = ((const float4*)gam)[lane];
    const float4 be4 = ((const float4*)bet)[lane];
    float gg[4] = {g4.x, g4.y, g4.z, g4.w};
    float ee2[4] = {be4.x, be4.y, be4.z, be4.w};
    float o4[4];
#pragma unroll
    for (int q = 0; q < 4; q++) {
        float o = (v4[q] - mu) * rstd * gg[q] + ee2[q];
        o4[q] = o > 0.f ? o : expm1f(o);
    }
    ((float4*)zv)[(size_t)d * 32 + lane] = make_float4(o4[0], o4[1], o4[2], o4[3]);
}

// ---------------- GRU (h_prev = 0) ----------------
__global__ void gru_kernel(const float* __restrict__ gi, const float* __restrict__ bhh,
                           float* __restrict__ h) {
    int idx = blockIdx.x * blockDim.x + threadIdx.x;
    if (idx >= N_NODES * 128) return;
    int n = idx >> 7, c = idx & 127;
    const float* g = gi + (size_t)n * 384;
    float r = 1.f / (1.f + expf(-(g[c] + bhh[c])));
    float u = 1.f / (1.f + expf(-(g[128 + c] + bhh[128 + c])));
    float ng = tanhf(g[256 + c] + r * bhh[256 + c]);
    h[idx] = (1.f - u) * ng;
}

// ---------------- classifier v8: 64 edges/block (3 blocks/SM), tc stage 2 ----------
// Same packed-pair tf32 layout as v7 but half-sized sO1 for higher occupancy.
#define C8_SO1_SLAB 520   // 64*8 + 8
#define C8_SW2_SLAB 520   // 64*8 + 8
#define C8_SO1_WORDS (16 * C8_SO1_SLAB)
#define C8_SW2_WORDS (16 * C8_SW2_SLAB)
#define C8_SEA_WORDS (64 * 16)
#define C8_PART_WORDS 128
#define C8_SMEM_WORDS (C8_SO1_WORDS + C8_SW2_WORDS + C8_SEA_WORDS + C8_PART_WORDS)
__global__ __launch_bounds__(256) void classifier8(
    const float* __restrict__ A, const float* __restrict__ B,
    const int* __restrict__ src, const int* __restrict__ dst,
    const float* __restrict__ ea, const float* __restrict__ Wc1c,
    const uint32_t* __restrict__ wc2p, const float* __restrict__ bc2,
    const float* __restrict__ Wc3, const float* __restrict__ bc3,
    float* __restrict__ out, int E) {
    extern __shared__ uint32_t smu[];
    uint32_t* sO1 = smu;                                  // packed o1 [16][64e][8]
    uint32_t* sW2 = smu + C8_SO1_WORDS;                   // packed Wc2 [16][64n][8]
    float* sEA = (float*)(smu + C8_SO1_WORDS + C8_SW2_WORDS);
    float* sPart = (float*)(smu + C8_SO1_WORDS + C8_SW2_WORDS + C8_SEA_WORDS);
    __shared__ int sSrc[64], sDst[64];
    const int tid = threadIdx.x;
    const int e0 = blockIdx.x * 64;

    // copy prepacked Wc2 (coalesced uint4, no remap)
    for (int w = tid * 4; w < 8192; w += 1024) {
        int g = w >> 9, rem = w & 511;
        *(uint4*)&sW2[g * C8_SW2_SLAB + rem] = *(const uint4*)&wc2p[w];
    }
    for (int idx = tid; idx < 64 * 16 / 4; idx += 256)
        ((float4*)sEA)[idx] = (e0 * 4 + idx < E * 4)
                                  ? ((const float4*)ea)[(size_t)e0 * 4 + idx]
                                  : make_float4(0.f, 0.f, 0.f, 0.f);
    if (tid < 64) {
        int ge = e0 + tid;
        sSrc[tid] = (ge < E) ? src[ge] : 0;
        sDst[tid] = (ge < E) ? dst[ge] : 0;
    }
    __syncthreads();

    // ---- stage 1: col = tid & 127, half = tid >> 7 handles 32 edges ----
    {
        const int col = tid & 127;
        const int half = tid >> 7;
        const int g = col >> 3;
        const int s = ((col & 3) << 1) | ((col >> 2) & 1);
        float w1c[16];
#pragma unroll
        for (int k = 0; k < 16; k++) w1c[k] = Wc1c[k * 128 + col];
        for (int i = 0; i < 32; i++) {
            int e = half * 32 + i;
            int ss = sSrc[e], dd = sDst[e];
            float acc = A[(size_t)ss * 128 + col] + B[(size_t)dd * 128 + col];
            const float4* ea4 = (const float4*)&sEA[e * 16];
#pragma unroll
            for (int k4 = 0; k4 < 4; k4++) {
                float4 v = ea4[k4];
                acc = fmaf(v.x, w1c[k4 * 4 + 0], acc);
                acc = fmaf(v.y, w1c[k4 * 4 + 1], acc);
                acc = fmaf(v.z, w1c[k4 * 4 + 2], acc);
                acc = fmaf(v.w, w1c[k4 * 4 + 3], acc);
            }
            sO1[g * C8_SO1_SLAB + e * 8 + s] = f2tf32(fmaxf(acc, 0.f));
        }
    }
    __syncthreads();

    // ---- stage 2: tf32 mma. 8 warps = 4 edge-groups (16e, m16) x 2 col-groups (32c) --
    {
        const int warp = tid >> 5, lane = tid & 31;
        const int lk = lane & 3, lr = lane >> 2;
        const int eg = warp >> 1;   // 0..3, edge base eg*16
        const int cg = warp & 1;    // col base cg*32
        float acc[4][4];
#pragma unroll
        for (int nt = 0; nt < 4; nt++)
#pragma unroll
            for (int i = 0; i < 4; i++) acc[nt][i] = 0.f;

#pragma unroll
        for (int g = 0; g < 16; g++) {
            uint32_t af[4];
            {
                int e = eg * 16 + lr;
                uint2 p0 = *(const uint2*)&sO1[g * C8_SO1_SLAB + e * 8 + lk * 2];
                uint2 p1 = *(const uint2*)&sO1[g * C8_SO1_SLAB + (e + 8) * 8 + lk * 2];
                af[0] = p0.x; af[2] = p0.y;
                af[1] = p1.x; af[3] = p1.y;
            }
#pragma unroll
            for (int nt = 0; nt < 4; nt++) {
                int n = cg * 32 + nt * 8 + lr;
                uint2 q = *(const uint2*)&sW2[g * C8_SW2_SLAB + n * 8 + lk * 2];
                uint32_t bf[2] = {q.x, q.y};
                mma_tf32(acc[nt], af, bf);
            }
        }

        // ---- fused stage 3 ----
        float p0 = 0.f, p1 = 0.f;
#pragma unroll
        for (int nt = 0; nt < 4; nt++) {
            int c = cg * 32 + nt * 8 + lk * 2;
            float bA = bc2[c], bB = bc2[c + 1];
            float wA = Wc3[c], wB = Wc3[c + 1];
            p0 = fmaf(fmaxf(acc[nt][0] + bA, 0.f), wA, p0);
            p0 = fmaf(fmaxf(acc[nt][1] + bB, 0.f), wB, p0);
            p1 = fmaf(fmaxf(acc[nt][2] + bA, 0.f), wA, p1);
            p1 = fmaf(fmaxf(acc[nt][3] + bB, 0.f), wB, p1);
        }
        p0 += __shfl_xor_sync(0xffffffffu, p0, 1);
        p0 += __shfl_xor_sync(0xffffffffu, p0, 2);
        p1 += __shfl_xor_sync(0xffffffffu, p1, 1);
        p1 += __shfl_xor_sync(0xffffffffu, p1, 2);
        if (lk == 0) {
            int r = eg * 16 + lr;
            sPart[cg * 64 + r] = p0;
            sPart[cg * 64 + r + 8] = p1;
        }
    }
    __syncthreads();
    if (tid < 64) {
        int ge = e0 + tid;
        if (ge < E) out[ge] = sPart[tid] + sPart[64 + tid] + bc3[0];
    }
}

// ---------------- launch ----------------
extern "C" void kernel_launch(void* const* d_in, const int* in_sizes, int n_in,
                              void* d_out, int out_size) {
    const float* x   = (const float*)d_in[0];
    const int*   ei  = (const int*)d_in[1];
    const float* ea  = (const float*)d_in[2];
    const float* Wl1 = (const float*)d_in[3];
    const float* bl1 = (const float*)d_in[4];
    const float* Wr1 = (const float*)d_in[5];
    const float* br1 = (const float*)d_in[6];
    const float* We1 = (const float*)d_in[7];
    const float* att1 = (const float*)d_in[8];
    const float* bias1 = (const float*)d_in[9];
    const float* g1 = (const float*)d_in[10];
    const float* be1 = (const float*)d_in[11];
    const float* Wl2 = (const float*)d_in[12];
    const float* bl2 = (const float*)d_in[13];
    const float* Wr2 = (const float*)d_in[14];
    const float* br2 = (const float*)d_in[15];
    const float* We2 = (const float*)d_in[16];
    const float* att2 = (const float*)d_in[17];
    const float* bias2 = (const float*)d_in[18];
    const float* g2 = (const float*)d_in[19];
    const float* be2 = (const float*)d_in[20];
    const float* W_ih = (const float*)d_in[21];
    /* W_hh d_in[22] unused: h_prev == 0 */
    const float* b_ih = (const float*)d_in[23];
    const float* b_hh = (const float*)d_in[24];
    const float* Wc1 = (const float*)d_in[25];
    const float* bc1 = (const float*)d_in[26];
    const float* Wc2 = (const float*)d_in[27];
    const float* bc2 = (const float*)d_in[28];
    const float* Wc3 = (const float*)d_in[29];
    const float* bc3 = (const float*)d_in[30];
    float* out = (float*)d_out;

    const int* src = ei;
    const int* dst = ei + N_EDGES;

    float *xl, *xr, *zv1, *zv2, *gi, *h, *Wt, *easum;
    uint32_t* wc2p;
    int *deg, *fill, *rowptr, *csr_src, *csr_eid;
    cudaGetSymbolAddress((void**)&xl, g_xl);
    cudaGetSymbolAddress((void**)&xr, g_xr);
    cudaGetSymbolAddress((void**)&zv1, g_zv1);
    cudaGetSymbolAddress((void**)&zv2, g_zv2);
    cudaGetSymbolAddress((void**)&gi, g_gi);
    cudaGetSymbolAddress((void**)&h, g_h);
    cudaGetSymbolAddress((void**)&Wt, g_Wt);
    cudaGetSymbolAddress((void**)&easum, g_easum);
    cudaGetSymbolAddress((void**)&wc2p, g_wc2p);
    cudaGetSymbolAddress((void**)&deg, g_deg);
    cudaGetSymbolAddress((void**)&fill, g_fill);
    cudaGetSymbolAddress((void**)&rowptr, g_rowptr);
    cudaGetSymbolAddress((void**)&csr_src, g_csr_src);
    cudaGetSymbolAddress((void**)&csr_eid, g_csr_eid);

    const float invE = 1.f / (float)N_EDGES;

    // one-time setup on the first (uncaptured) call: streams, events, smem attr
    static cudaStream_t s1 = nullptr, s2 = nullptr;
    static cudaEvent_t ev[3];
    if (!s1) {
        cudaFuncSetAttribute(classifier8, cudaFuncAttributeMaxDynamicSharedMemorySize,
                             C8_SMEM_WORDS * sizeof(uint32_t));
        cudaStreamCreateWithFlags(&s1, cudaStreamNonBlocking);
        cudaStreamCreateWithFlags(&s2, cudaStreamNonBlocking);
        for (int i = 0; i < 3; i++) cudaEventCreateWithFlags(&ev[i], cudaEventDisableTiming);
    }

    const int NB = (N_NODES + 127) / 128;  // 157 row-blocks

    // ---- fork: s1 = CSR build chain, s2 = transpose + Wc2 pack, s0 = easum + xl1|xr1 ----
    cudaEventRecord(ev[0], 0);
    cudaStreamWaitEvent(s1, ev[0], 0);
    cudaStreamWaitEvent(s2, ev[0], 0);

    // s1: CSR chain
    zero2_i<<<(N_NODES + 255) / 256, 256, 0, s1>>>(deg, fill, N_NODES);
    deg_count<<<(N_EDGES + 255) / 256, 256, 0, s1>>>(dst, deg);
    scan_kernel<<<1, 1024, 0, s1>>>(deg, rowptr);
    scatter_kernel<<<(N_ITEMS + 255) / 256, 256, 0, s1>>>(src, dst, rowptr, fill,
                                                          csr_src, csr_eid);
    cudaEventRecord(ev[1], s1);

    // s2: transpose + Wc2 pack
    transpose_wih<<<(384 * 128 + 255) / 256, 256, 0, s2>>>(W_ih, Wt);
    pack_wc2<<<32, 256, 0, s2>>>(Wc2, wc2p);
    cudaEventRecord(ev[2], s2);

    // s0: edge-attr mean + fused xl1|xr1 dual GEMM (628 blocks)
    zero_f<<<1, 32>>>(easum, 16);
    ea_colsum4<<<256, 256>>>(ea, easum);
    {
        dim3 grid(4, NB);
        gemm_tc2<<<grid, 256>>>(x, Wl1, bl1, xl, Wr1, br1, xr, N_NODES, 128, 256, 2);
    }

    // ---- join, GAT layer 1 (heads=2, EP=2) ----
    cudaStreamWaitEvent(0, ev[1], 0);
    cudaStreamWaitEvent(0, ev[2], 0);
    gat_fused_b<2, 2><<<(N_NODES + 7) / 8, 256>>>(rowptr, csr_src, csr_eid, ea, We1,
                                                  easum, invE, xl, xr, att1, bias1,
                                                  g1, be1, zv1);

    // ---- layer 2: fused xl2|xr2 dual GEMM (314 blocks) ----
    {
        dim3 grid(2, NB);
        gemm_tc2<<<grid, 256>>>(zv1, Wl2, bl2, xl, Wr2, br2, xr, N_NODES, 128, 128, 1);
    }
    gat_fused_b<1, 4><<<(N_NODES + 7) / 8, 256>>>(rowptr, csr_src, csr_eid, ea, We2,
                                                  easum, invE, xl, xr, att2, bias2,
                                                  g2, be2, zv2);

    // ---- GRU (h_prev = 0) ----
    {
        dim3 grid(3, NB);
        gemm_tc2<<<grid, 256>>>(zv2, Wt, b_ih, gi,
                                (const float*)nullptr, (const float*)nullptr,
                                (float*)nullptr, N_NODES, 128, 384, 3);
    }
    gru_kernel<<<(N_NODES * 128 + 255) / 256, 256>>>(gi, b_hh, h);

    // ---- classifier: fused A|B dual GEMM, then fused edge MLP (tensor-core) ----
    float* Amat = xl;
    float* Bmat = xl + (size_t)N_NODES * 128;
    {
        dim3 grid(2, NB);
        gemm_tc2<<<grid, 256>>>(h, Wc1, bc1, Amat,
                                Wc1 + 128 * 128, (const float*)nullptr, Bmat,
                                N_NODES, 128, 128, 1);
    }
    classifier8<<<(N_EDGES + 63) / 64, 256, C8_SMEM_WORDS * sizeof(uint32_t)>>>(
        Amat, Bmat, src, dst, ea, Wc1 + 256 * 128, wc2p, bc2, Wc3, bc3, out, N_EDGES);
}

// round 16
// speedup vs baseline: 1.1425x; 1.0664x over previous
#include <cuda_runtime.h>
#include <math.h>
#include <stdint.h>

#define N_NODES 20000
#define N_EDGES 320000
#define N_ITEMS (N_EDGES + N_NODES)

// ---------------- scratch (device globals; no allocs allowed) ----------------
__device__ float g_xl[N_NODES * 256];
__device__ float g_xr[N_NODES * 256];
__device__ float g_zv1[N_NODES * 128];
__device__ float g_zv2[N_NODES * 128];
__device__ float g_gi[N_NODES * 384];
__device__ float g_h[N_NODES * 128];
__device__ float g_Wt[128 * 384];
__device__ float g_easum[16];
__device__ uint32_t g_wc2p[8192];   // packed tf32 Wc2 [g][n][s], slab 512 (L2-resident)
__device__ int g_deg[N_NODES];
__device__ int g_fill[N_NODES];
__device__ int g_rowptr[N_NODES + 1];
__device__ int g_csr_src[N_ITEMS];
__device__ int g_csr_eid[N_ITEMS];

// ---------------- utility kernels ----------------
__global__ void zero_f(float* p, int n) {
    int i = blockIdx.x * blockDim.x + threadIdx.x;
    if (i < n) p[i] = 0.f;
}
__global__ void zero2_i(int* p0, int* p1, int n) {
    int i = blockIdx.x * blockDim.x + threadIdx.x;
    if (i < n) { p0[i] = 0; p1[i] = 0; }
}

__global__ void ea_colsum4(const float* __restrict__ ea, float* easum) {
    __shared__ float sh[16];
    if (threadIdx.x < 16) sh[threadIdx.x] = 0.f;
    __syncthreads();
    int g = blockIdx.x * blockDim.x + threadIdx.x;
    int stride = gridDim.x * blockDim.x;
    int q = g & 3;
    int slot = g >> 2;
    int ns = stride >> 2;
    float4 acc = make_float4(0.f, 0.f, 0.f, 0.f);
    for (int e = slot; e < N_EDGES; e += ns) {
        float4 v = *(const float4*)&ea[(size_t)e * 16 + q * 4];
        acc.x += v.x; acc.y += v.y; acc.z += v.z; acc.w += v.w;
    }
    atomicAdd(&sh[q * 4 + 0], acc.x);
    atomicAdd(&sh[q * 4 + 1], acc.y);
    atomicAdd(&sh[q * 4 + 2], acc.z);
    atomicAdd(&sh[q * 4 + 3], acc.w);
    __syncthreads();
    if (threadIdx.x < 16) atomicAdd(&easum[threadIdx.x], sh[threadIdx.x]);
}

__global__ void transpose_wih(const float* __restrict__ W, float* __restrict__ Wt) {
    int i = blockIdx.x * blockDim.x + threadIdx.x;
    if (i < 384 * 128) {
        int j = i / 128, k = i % 128;
        Wt[k * 384 + j] = W[i];
    }
}

// ---------------- tf32 helpers ----------------
__device__ __forceinline__ uint32_t f2tf32(float x) {
    uint32_t r;
    asm("cvt.rna.tf32.f32 %0, %1;" : "=r"(r) : "f"(x));
    return r;
}
__device__ __forceinline__ void mma_tf32(float* c, const uint32_t* a, const uint32_t* b) {
    asm volatile(
        "mma.sync.aligned.m16n8k8.row.col.f32.tf32.tf32.f32 "
        "{%0,%1,%2,%3}, {%4,%5,%6,%7}, {%8,%9}, {%0,%1,%2,%3};"
        : "+f"(c[0]), "+f"(c[1]), "+f"(c[2]), "+f"(c[3])
        : "r"(a[0]), "r"(a[1]), "r"(a[2]), "r"(a[3]), "r"(b[0]), "r"(b[1]));
}

// pack Wc2 [128k][64n] into tf32 words laid out [g=k/8][n][s], s=((k&3)<<1)|((k>>2)&1)
__global__ void pack_wc2(const float* __restrict__ Wc2, uint32_t* __restrict__ wc2p) {
    int w = blockIdx.x * blockDim.x + threadIdx.x;
    if (w < 8192) {
        int g = w >> 9, rem = w & 511, n = rem >> 3, s = rem & 7;
        int k = g * 8 + (s & 1) * 4 + (s >> 1);
        wc2p[w] = f2tf32(Wc2[k * 64 + n]);
    }
}

// ---------------- CSR build ----------------
__global__ void deg_count(const int* __restrict__ dst, int* __restrict__ deg) {
    int i = blockIdx.x * blockDim.x + threadIdx.x;
    if (i < N_EDGES) atomicAdd(&deg[dst[i]], 1);
}

__global__ void scan_kernel(const int* __restrict__ deg, int* __restrict__ rowptr) {
    __shared__ int ssum[1024];
    const int CH = 20;
    int t = threadIdx.x;
    int base = t * CH;
    int s = 0;
    for (int i = 0; i < CH; i++) {
        int node = base + i;
        if (node < N_NODES) s += deg[node] + 1;
    }
    ssum[t] = s;
    __syncthreads();
    for (int off = 1; off < 1024; off <<= 1) {
        int v = (t >= off) ? ssum[t - off] : 0;
        __syncthreads();
        ssum[t] += v;
        __syncthreads();
    }
    int run = (t == 0) ? 0 : ssum[t - 1];
    for (int i = 0; i < CH; i++) {
        int node = base + i;
        if (node < N_NODES) {
            rowptr[node] = run;
            run += deg[node] + 1;
        } else if (node == N_NODES) {
            rowptr[node] = run;
        }
    }
}

__global__ void scatter_kernel(const int* __restrict__ src, const int* __restrict__ dst,
                               const int* __restrict__ rowptr, int* __restrict__ fill,
                               int* __restrict__ csr_src, int* __restrict__ csr_eid) {
    int i = blockIdx.x * blockDim.x + threadIdx.x;
    if (i >= N_ITEMS) return;
    int s, d;
    if (i < N_EDGES) { s = src[i]; d = dst[i]; }
    else { s = i - N_EDGES; d = s; }
    int pos = rowptr[d] + atomicAdd(&fill[d], 1);
    csr_src[pos] = s;
    csr_eid[pos] = i;
}

// ---------------- tf32 tensor-core GEMM, dual-output, reg-prefetch pipelined ----------
__global__ __launch_bounds__(256) void gemm_tc2(
    const float* __restrict__ A,
    const float* __restrict__ B0, const float* __restrict__ bias0, float* __restrict__ C0,
    const float* __restrict__ B1, const float* __restrict__ bias1, float* __restrict__ C1,
    int n, int K, int M, int gx0) {
    __shared__ uint32_t As[16][132];
    __shared__ uint32_t Bs[16][132];
    const int tid = threadIdx.x;
    const int warp = tid >> 5, lane = tid & 31;
    const int warpM = (warp >> 1) * 32;
    const int warpN = (warp & 1) * 64;
    int bx = blockIdx.x;
    const float* B;
    const float* bias;
    float* C;
    if (bx < gx0) { B = B0; bias = bias0; C = C0; }
    else { bx -= gx0; B = B1; bias = bias1; C = C1; }
    const int row0 = blockIdx.y * 128, col0 = bx * 128;
    const int lk = lane & 3;
    const int lr = lane >> 2;

    int arow[2], aq[2], brow[2], bq[2];
#pragma unroll
    for (int i = 0; i < 2; i++) {
        int idx = tid * 2 + i;
        arow[i] = idx >> 2;
        aq[i] = idx & 3;
        brow[i] = idx >> 5;
        bq[i] = idx & 31;
    }

    float acc[2][8][4] = {};
    float4 pa[2], pb[2];

#pragma unroll
    for (int i = 0; i < 2; i++) {
        int r = row0 + arow[i];
        pa[i] = (r < n) ? *(const float4*)&A[(size_t)r * K + aq[i] * 4]
                        : make_float4(0.f, 0.f, 0.f, 0.f);
        pb[i] = *(const float4*)&B[(size_t)brow[i] * M + col0 + bq[i] * 4];
    }

    for (int k0 = 0; k0 < K; k0 += 16) {
#pragma unroll
        for (int i = 0; i < 2; i++) {
            As[aq[i] * 4 + 0][arow[i]] = f2tf32(pa[i].x);
            As[aq[i] * 4 + 1][arow[i]] = f2tf32(pa[i].y);
            As[aq[i] * 4 + 2][arow[i]] = f2tf32(pa[i].z);
            As[aq[i] * 4 + 3][arow[i]] = f2tf32(pa[i].w);
            uint4 tv;
            tv.x = f2tf32(pb[i].x); tv.y = f2tf32(pb[i].y);
            tv.z = f2tf32(pb[i].z); tv.w = f2tf32(pb[i].w);
            *(uint4*)&Bs[brow[i]][bq[i] * 4] = tv;
        }
        __syncthreads();
        if (k0 + 16 < K) {
#pragma unroll
            for (int i = 0; i < 2; i++) {
                int r = row0 + arow[i];
                pa[i] = (r < n) ? *(const float4*)&A[(size_t)r * K + k0 + 16 + aq[i] * 4]
                                : make_float4(0.f, 0.f, 0.f, 0.f);
                pb[i] = *(const float4*)&B[(size_t)(k0 + 16 + brow[i]) * M + col0 + bq[i] * 4];
            }
        }
#pragma unroll
        for (int ks = 0; ks < 16; ks += 8) {
            uint32_t af[2][4];
#pragma unroll
            for (int mt = 0; mt < 2; mt++) {
                int m = warpM + mt * 16 + lr;
                af[mt][0] = As[ks + lk][m];
                af[mt][1] = As[ks + lk][m + 8];
                af[mt][2] = As[ks + lk + 4][m];
                af[mt][3] = As[ks + lk + 4][m + 8];
            }
            uint32_t bf[8][2];
#pragma unroll
            for (int nt = 0; nt < 8; nt++) {
                int nn = warpN + nt * 8 + lr;
                bf[nt][0] = Bs[ks + lk][nn];
                bf[nt][1] = Bs[ks + lk + 4][nn];
            }
#pragma unroll
            for (int mt = 0; mt < 2; mt++)
#pragma unroll
                for (int nt = 0; nt < 8; nt++) mma_tf32(acc[mt][nt], af[mt], bf[nt]);
        }
        __syncthreads();
    }
#pragma unroll
    for (int mt = 0; mt < 2; mt++) {
        int r0 = row0 + warpM + mt * 16 + lr;
        int r1 = r0 + 8;
#pragma unroll
        for (int nt = 0; nt < 8; nt++) {
            int c = col0 + warpN + nt * 8 + lk * 2;
            float b0 = bias ? bias[c] : 0.f;
            float b1 = bias ? bias[c + 1] : 0.f;
            if (r0 < n) {
                float2 v = make_float2(acc[mt][nt][0] + b0, acc[mt][nt][1] + b1);
                *(float2*)&C[(size_t)r0 * M + c] = v;
            }
            if (r1 < n) {
                float2 v = make_float2(acc[mt][nt][2] + b0, acc[mt][nt][3] + b1);
                *(float2*)&C[(size_t)r1 * M + c] = v;
            }
        }
    }
}

// ---------------- fused single-pass GATv2, edge-batched (EP edges share We loads) ----
template <int HEADS, int EP>
__global__ __launch_bounds__(256) void gat_fused_b(
    const int* __restrict__ rowptr, const int* __restrict__ csr_src,
    const int* __restrict__ csr_eid, const float* __restrict__ ea,
    const float* __restrict__ We, const float* __restrict__ easum, float invE,
    const float* __restrict__ xl, const float* __restrict__ xr,
    const float* __restrict__ att, const float* __restrict__ bias,
    const float* __restrict__ gam, const float* __restrict__ bet,
    float* __restrict__ zv) {
    constexpr int M = HEADS * 128;
    constexpr int F = M / 4;
    __shared__ float4 sWe[16 * F];
    __shared__ float4 sAtt[F];
    __shared__ float sMean[16];
    for (int i = threadIdx.x; i < 16 * F; i += blockDim.x)
        sWe[i] = ((const float4*)We)[i];
    for (int i = threadIdx.x; i < F; i += blockDim.x)
        sAtt[i] = ((const float4*)att)[i];
    if (threadIdx.x < 16) sMean[threadIdx.x] = easum[threadIdx.x] * invE;
    __syncthreads();

    int warp = (blockIdx.x * blockDim.x + threadIdx.x) >> 5;
    int lane = threadIdx.x & 31;
    if (warp >= N_NODES) return;
    int d = warp;
    int beg = rowptr[d], end = rowptr[d + 1];
    const float4* xl4 = (const float4*)xl;
    const float4* xr4 = (const float4*)xr;

    float4 xrr[HEADS];
#pragma unroll
    for (int t = 0; t < HEADS; t++) xrr[t] = xr4[(size_t)d * F + t * 32 + lane];

    float4 num[HEADS];
    float den[HEADS];
#pragma unroll
    for (int t = 0; t < HEADS; t++) {
        num[t] = make_float4(0.f, 0.f, 0.f, 0.f);
        den[t] = 0.f;
    }

    for (int p = beg; p < end; p += EP) {
        int ne = end - p;
        if (ne > EP) ne = EP;
        int sidx[EP];
        float eav[EP];
#pragma unroll
        for (int e = 0; e < EP; e++) {
            int idx = p + (e < ne ? e : ne - 1);
            sidx[e] = csr_src[idx];
            int eid = csr_eid[idx];
            bool lp = eid >= N_EDGES;
            eav[e] = (lane < 16)
                         ? (lp ? sMean[lane] : ea[(size_t)eid * 16 + lane])
                         : 0.f;
        }
#pragma unroll
        for (int t = 0; t < HEADS; t++) {
            float4 xlv[EP], eev[EP];
#pragma unroll
            for (int e = 0; e < EP; e++) {
                xlv[e] = xl4[(size_t)sidx[e] * F + t * 32 + lane];
                eev[e] = make_float4(0.f, 0.f, 0.f, 0.f);
            }
#pragma unroll
            for (int k = 0; k < 16; k++) {
                float4 w = sWe[k * F + t * 32 + lane];
#pragma unroll
                for (int e = 0; e < EP; e++) {
                    float ek = __shfl_sync(0xffffffffu, eav[e], k);
                    eev[e].x = fmaf(ek, w.x, eev[e].x);
                    eev[e].y = fmaf(ek, w.y, eev[e].y);
                    eev[e].z = fmaf(ek, w.z, eev[e].z);
                    eev[e].w = fmaf(ek, w.w, eev[e].w);
                }
            }
            float4 a4 = sAtt[t * 32 + lane];
#pragma unroll
            for (int e = 0; e < EP; e++) {
                float mx = xlv[e].x + xrr[t].x + eev[e].x;
                float my = xlv[e].y + xrr[t].y + eev[e].y;
                float mz = xlv[e].z + xrr[t].z + eev[e].z;
                float mw = xlv[e].w + xrr[t].w + eev[e].w;
                mx = mx > 0.f ? mx : 0.2f * mx;
                my = my > 0.f ? my : 0.2f * my;
                mz = mz > 0.f ? mz : 0.2f * mz;
                mw = mw > 0.f ? mw : 0.2f * mw;
                float sc = fmaf(mx, a4.x, fmaf(my, a4.y, fmaf(mz, a4.z, mw * a4.w)));
#pragma unroll
                for (int o = 16; o > 0; o >>= 1)
                    sc += __shfl_xor_sync(0xffffffffu, sc, o);
                if (e < ne) {
                    float exv = expf(sc);
                    den[t] += exv;
                    num[t].x = fmaf(exv, xlv[e].x, num[t].x);
                    num[t].y = fmaf(exv, xlv[e].y, num[t].y);
                    num[t].z = fmaf(exv, xlv[e].z, num[t].z);
                    num[t].w = fmaf(exv, xlv[e].w, num[t].w);
                }
            }
        }
    }
    float inv[HEADS];
#pragma unroll
    for (int t = 0; t < HEADS; t++) inv[t] = 1.f / (den[t] + 1e-16f);

    float v4[4];
    {
        const float4 b4 = ((const float4*)bias)[lane];
        float n0[4] = {num[0].x, num[0].y, num[0].z, num[0].w};
        float bb[4] = {b4.x, b4.y, b4.z, b4.w};
        float n1[4];
        if (HEADS == 2) { n1[0] = num[1].x; n1[1] = num[1].y; n1[2] = num[1].z; n1[3] = num[1].w; }
#pragma unroll
        for (int q = 0; q < 4; q++) {
            float a = n0[q] * inv[0];
            if (HEADS == 2) a = 0.5f * (a + n1[q] * inv[1]);
            v4[q] = a + bb[q];
        }
    }
    float s = v4[0] + v4[1] + v4[2] + v4[3];
#pragma unroll
    for (int o = 16; o > 0; o >>= 1) s += __shfl_xor_sync(0xffffffffu, s, o);
    float mu = s * (1.f / 128.f);
    float vs = 0.f;
#pragma unroll
    for (int q = 0; q < 4; q++) {
        float dd = v4[q] - mu;
        vs = fmaf(dd, dd, vs);
    }
#pragma unroll
    for (int o = 16; o > 0; o >>= 1) vs += __shfl_xor_sync(0xffffffffu, vs, o);
    float rstd = rsqrtf(vs * (1.f / 128.f) + 1e-5f);
    const float4 g4 = ((const float4*)gam)[lane];
    const float4 be4 = ((const float4*)bet)[lane];
    float gg[4] = {g4.x, g4.y, g4.z, g4.w};
    float ee2[4] = {be4.x, be4.y, be4.z, be4.w};
    float o4[4];
#pragma unroll
    for (int q = 0; q < 4; q++) {
        float o = (v4[q] - mu) * rstd * gg[q] + ee2[q];
        o4[q] = o > 0.f ? o : expm1f(o);
    }
    ((float4*)zv)[(size_t)d * 32 + lane] = make_float4(o4[0], o4[1], o4[2], o4[3]);
}

// ---------------- GRU (h_prev = 0) ----------------
__global__ void gru_kernel(const float* __restrict__ gi, const float* __restrict__ bhh,
                           float* __restrict__ h) {
    int idx = blockIdx.x * blockDim.x + threadIdx.x;
    if (idx >= N_NODES * 128) return;
    int n = idx >> 7, c = idx & 127;
    const float* g = gi + (size_t)n * 384;
    float r = 1.f / (1.f + expf(-(g[c] + bhh[c])));
    float u = 1.f / (1.f + expf(-(g[128 + c] + bhh[128 + c])));
    float ng = tanhf(g[256 + c] + r * bhh[256 + c]);
    h[idx] = (1.f - u) * ng;
}

// ---------------- classifier v9: 64 edges/block, Wc2 fragments direct from global ----
// sW2 eliminated: stage-2 B fragments are coalesced LDG.64 from L2-resident g_wc2p
// (all blocks share the same 32 KB). smem ~37 KB -> ~6 blocks/SM for gather hiding.
#define C9_SO1_SLAB 520   // 64*8 + 8
#define C9_SO1_WORDS (16 * C9_SO1_SLAB)
#define C9_SEA_WORDS (64 * 16)
#define C9_PART_WORDS 128
#define C9_SMEM_WORDS (C9_SO1_WORDS + C9_SEA_WORDS + C9_PART_WORDS)
__global__ __launch_bounds__(256) void classifier9(
    const float* __restrict__ A, const float* __restrict__ B,
    const int* __restrict__ src, const int* __restrict__ dst,
    const float* __restrict__ ea, const float* __restrict__ Wc1c,
    const uint32_t* __restrict__ wc2p, const float* __restrict__ bc2,
    const float* __restrict__ Wc3, const float* __restrict__ bc3,
    float* __restrict__ out, int E) {
    extern __shared__ uint32_t smu[];
    uint32_t* sO1 = smu;                                  // packed o1 [16][64e][8]
    float* sEA = (float*)(smu + C9_SO1_WORDS);
    float* sPart = (float*)(smu + C9_SO1_WORDS + C9_SEA_WORDS);
    __shared__ int sSrc[64], sDst[64];
    const int tid = threadIdx.x;
    const int e0 = blockIdx.x * 64;

    for (int idx = tid; idx < 64 * 16 / 4; idx += 256)
        ((float4*)sEA)[idx] = (e0 * 4 + idx < E * 4)
                                  ? ((const float4*)ea)[(size_t)e0 * 4 + idx]
                                  : make_float4(0.f, 0.f, 0.f, 0.f);
    if (tid < 64) {
        int ge = e0 + tid;
        sSrc[tid] = (ge < E) ? src[ge] : 0;
        sDst[tid] = (ge < E) ? dst[ge] : 0;
    }
    __syncthreads();

    // ---- stage 1: col = tid & 127, half = tid >> 7 handles 32 edges ----
    {
        const int col = tid & 127;
        const int half = tid >> 7;
        const int g = col >> 3;
        const int s = ((col & 3) << 1) | ((col >> 2) & 1);
        float w1c[16];
#pragma unroll
        for (int k = 0; k < 16; k++) w1c[k] = Wc1c[k * 128 + col];
        for (int i = 0; i < 32; i++) {
            int e = half * 32 + i;
            int ss = sSrc[e], dd = sDst[e];
            float acc = A[(size_t)ss * 128 + col] + B[(size_t)dd * 128 + col];
            const float4* ea4 = (const float4*)&sEA[e * 16];
#pragma unroll
            for (int k4 = 0; k4 < 4; k4++) {
                float4 v = ea4[k4];
                acc = fmaf(v.x, w1c[k4 * 4 + 0], acc);
                acc = fmaf(v.y, w1c[k4 * 4 + 1], acc);
                acc = fmaf(v.z, w1c[k4 * 4 + 2], acc);
                acc = fmaf(v.w, w1c[k4 * 4 + 3], acc);
            }
            sO1[g * C9_SO1_SLAB + e * 8 + s] = f2tf32(fmaxf(acc, 0.f));
        }
    }
    __syncthreads();

    // ---- stage 2: tf32 mma; B fragments via coalesced LDG.64 from wc2p ----
    {
        const int warp = tid >> 5, lane = tid & 31;
        const int lk = lane & 3, lr = lane >> 2;
        const int eg = warp >> 1;   // edge base eg*16
        const int cg = warp & 1;    // col base cg*32
        float acc[4][4];
#pragma unroll
        for (int nt = 0; nt < 4; nt++)
#pragma unroll
            for (int i = 0; i < 4; i++) acc[nt][i] = 0.f;

#pragma unroll
        for (int g = 0; g < 16; g++) {
            uint32_t af[4];
            {
                int e = eg * 16 + lr;
                uint2 p0 = *(const uint2*)&sO1[g * C9_SO1_SLAB + e * 8 + lk * 2];
                uint2 p1 = *(const uint2*)&sO1[g * C9_SO1_SLAB + (e + 8) * 8 + lk * 2];
                af[0] = p0.x; af[2] = p0.y;
                af[1] = p1.x; af[3] = p1.y;
            }
#pragma unroll
            for (int nt = 0; nt < 4; nt++) {
                int n = cg * 32 + nt * 8 + lr;
                uint2 q = *(const uint2*)&wc2p[g * 512 + n * 8 + lk * 2];
                uint32_t bf[2] = {q.x, q.y};
                mma_tf32(acc[nt], af, bf);
            }
        }

        // ---- fused stage 3 ----
        float p0 = 0.f, p1 = 0.f;
#pragma unroll
        for (int nt = 0; nt < 4; nt++) {
            int c = cg * 32 + nt * 8 + lk * 2;
            float bA = bc2[c], bB = bc2[c + 1];
            float wA = Wc3[c], wB = Wc3[c + 1];
            p0 = fmaf(fmaxf(acc[nt][0] + bA, 0.f), wA, p0);
            p0 = fmaf(fmaxf(acc[nt][1] + bB, 0.f), wB, p0);
            p1 = fmaf(fmaxf(acc[nt][2] + bA, 0.f), wA, p1);
            p1 = fmaf(fmaxf(acc[nt][3] + bB, 0.f), wB, p1);
        }
        p0 += __shfl_xor_sync(0xffffffffu, p0, 1);
        p0 += __shfl_xor_sync(0xffffffffu, p0, 2);
        p1 += __shfl_xor_sync(0xffffffffu, p1, 1);
        p1 += __shfl_xor_sync(0xffffffffu, p1, 2);
        if (lk == 0) {
            int r = eg * 16 + lr;
            sPart[cg * 64 + r] = p0;
            sPart[cg * 64 + r + 8] = p1;
        }
    }
    __syncthreads();
    if (tid < 64) {
        int ge = e0 + tid;
        if (ge < E) out[ge] = sPart[tid] + sPart[64 + tid] + bc3[0];
    }
}

// ---------------- launch ----------------
extern "C" void kernel_launch(void* const* d_in, const int* in_sizes, int n_in,
                              void* d_out, int out_size) {
    const float* x   = (const float*)d_in[0];
    const int*   ei  = (const int*)d_in[1];
    const float* ea  = (const float*)d_in[2];
    const float* Wl1 = (const float*)d_in[3];
    const float* bl1 = (const float*)d_in[4];
    const float* Wr1 = (const float*)d_in[5];
    const float* br1 = (const float*)d_in[6];
    const float* We1 = (const float*)d_in[7];
    const float* att1 = (const float*)d_in[8];
    const float* bias1 = (const float*)d_in[9];
    const float* g1 = (const float*)d_in[10];
    const float* be1 = (const float*)d_in[11];
    const float* Wl2 = (const float*)d_in[12];
    const float* bl2 = (const float*)d_in[13];
    const float* Wr2 = (const float*)d_in[14];
    const float* br2 = (const float*)d_in[15];
    const float* We2 = (const float*)d_in[16];
    const float* att2 = (const float*)d_in[17];
    const float* bias2 = (const float*)d_in[18];
    const float* g2 = (const float*)d_in[19];
    const float* be2 = (const float*)d_in[20];
    const float* W_ih = (const float*)d_in[21];
    /* W_hh d_in[22] unused: h_prev == 0 */
    const float* b_ih = (const float*)d_in[23];
    const float* b_hh = (const float*)d_in[24];
    const float* Wc1 = (const float*)d_in[25];
    const float* bc1 = (const float*)d_in[26];
    const float* Wc2 = (const float*)d_in[27];
    const float* bc2 = (const float*)d_in[28];
    const float* Wc3 = (const float*)d_in[29];
    const float* bc3 = (const float*)d_in[30];
    float* out = (float*)d_out;

    const int* src = ei;
    const int* dst = ei + N_EDGES;

    float *xl, *xr, *zv1, *zv2, *gi, *h, *Wt, *easum;
    uint32_t* wc2p;
    int *deg, *fill, *rowptr, *csr_src, *csr_eid;
    cudaGetSymbolAddress((void**)&xl, g_xl);
    cudaGetSymbolAddress((void**)&xr, g_xr);
    cudaGetSymbolAddress((void**)&zv1, g_zv1);
    cudaGetSymbolAddress((void**)&zv2, g_zv2);
    cudaGetSymbolAddress((void**)&gi, g_gi);
    cudaGetSymbolAddress((void**)&h, g_h);
    cudaGetSymbolAddress((void**)&Wt, g_Wt);
    cudaGetSymbolAddress((void**)&easum, g_easum);
    cudaGetSymbolAddress((void**)&wc2p, g_wc2p);
    cudaGetSymbolAddress((void**)&deg, g_deg);
    cudaGetSymbolAddress((void**)&fill, g_fill);
    cudaGetSymbolAddress((void**)&rowptr, g_rowptr);
    cudaGetSymbolAddress((void**)&csr_src, g_csr_src);
    cudaGetSymbolAddress((void**)&csr_eid, g_csr_eid);

    const float invE = 1.f / (float)N_EDGES;

    // one-time setup on the first (uncaptured) call: streams, events, smem attr
    static cudaStream_t s1 = nullptr, s2 = nullptr;
    static cudaEvent_t ev[3];
    if (!s1) {
        cudaFuncSetAttribute(classifier9, cudaFuncAttributeMaxDynamicSharedMemorySize,
                             C9_SMEM_WORDS * sizeof(uint32_t));
        cudaStreamCreateWithFlags(&s1, cudaStreamNonBlocking);
        cudaStreamCreateWithFlags(&s2, cudaStreamNonBlocking);
        for (int i = 0; i < 3; i++) cudaEventCreateWithFlags(&ev[i], cudaEventDisableTiming);
    }

    const int NB = (N_NODES + 127) / 128;  // 157 row-blocks

    // ---- fork: s1 = CSR build chain, s2 = transpose + Wc2 pack, s0 = easum + xl1|xr1 ----
    cudaEventRecord(ev[0], 0);
    cudaStreamWaitEvent(s1, ev[0], 0);
    cudaStreamWaitEvent(s2, ev[0], 0);

    // s1: CSR chain
    zero2_i<<<(N_NODES + 255) / 256, 256, 0, s1>>>(deg, fill, N_NODES);
    deg_count<<<(N_EDGES + 255) / 256, 256, 0, s1>>>(dst, deg);
    scan_kernel<<<1, 1024, 0, s1>>>(deg, rowptr);
    scatter_kernel<<<(N_ITEMS + 255) / 256, 256, 0, s1>>>(src, dst, rowptr, fill,
                                                          csr_src, csr_eid);
    cudaEventRecord(ev[1], s1);

    // s2: transpose + Wc2 pack
    transpose_wih<<<(384 * 128 + 255) / 256, 256, 0, s2>>>(W_ih, Wt);
    pack_wc2<<<32, 256, 0, s2>>>(Wc2, wc2p);
    cudaEventRecord(ev[2], s2);

    // s0: edge-attr mean + fused xl1|xr1 dual GEMM (628 blocks)
    zero_f<<<1, 32>>>(easum, 16);
    ea_colsum4<<<256, 256>>>(ea, easum);
    {
        dim3 grid(4, NB);
        gemm_tc2<<<grid, 256>>>(x, Wl1, bl1, xl, Wr1, br1, xr, N_NODES, 128, 256, 2);
    }

    // ---- join, GAT layer 1 (heads=2, EP=2) ----
    cudaStreamWaitEvent(0, ev[1], 0);
    cudaStreamWaitEvent(0, ev[2], 0);
    gat_fused_b<2, 2><<<(N_NODES + 7) / 8, 256>>>(rowptr, csr_src, csr_eid, ea, We1,
                                                  easum, invE, xl, xr, att1, bias1,
                                                  g1, be1, zv1);

    // ---- layer 2: fused xl2|xr2 dual GEMM (314 blocks) ----
    {
        dim3 grid(2, NB);
        gemm_tc2<<<grid, 256>>>(zv1, Wl2, bl2, xl, Wr2, br2, xr, N_NODES, 128, 128, 1);
    }
    gat_fused_b<1, 4><<<(N_NODES + 7) / 8, 256>>>(rowptr, csr_src, csr_eid, ea, We2,
                                                  easum, invE, xl, xr, att2, bias2,
                                                  g2, be2, zv2);

    // ---- GRU (h_prev = 0) ----
    {
        dim3 grid(3, NB);
        gemm_tc2<<<grid, 256>>>(zv2, Wt, b_ih, gi,
                                (const float*)nullptr, (const float*)nullptr,
                                (float*)nullptr, N_NODES, 128, 384, 3);
    }
    gru_kernel<<<(N_NODES * 128 + 255) / 256, 256>>>(gi, b_hh, h);

    // ---- classifier: fused A|B dual GEMM, then fused edge MLP (tensor-core) ----
    float* Amat = xl;
    float* Bmat = xl + (size_t)N_NODES * 128;
    {
        dim3 grid(2, NB);
        gemm_tc2<<<grid, 256>>>(h, Wc1, bc1, Amat,
                                Wc1 + 128 * 128, (const float*)nullptr, Bmat,
                                N_NODES, 128, 128, 1);
    }
    classifier9<<<(N_EDGES + 63) / 64, 256, C9_SMEM_WORDS * sizeof(uint32_t)>>>(
        Amat, Bmat, src, dst, ea, Wc1 + 256 * 128, wc2p, bc2, Wc3, bc3, out, N_EDGES);
}